// round 6
// baseline (speedup 1.0000x reference)
#include <cuda_runtime.h>
#include <cstdint>

#define N_NODES 100000
#define EDGES   640000
#define LAYERS  5
#define BN_EPS  1e-5f
#define NT      782
#define GRID_G  148
#define NSCAN   98

// ---------------- static scratch ------------------------------------------------
__device__ char  g_a8[2 * (size_t)N_NODES * 128];   // int8 digit planes of agg
__device__ float g_sa[N_NODES];
__device__ char  g_z8[2 * (size_t)N_NODES * 256];   // int8 digit planes of z
__device__ float g_sz[N_NODES];
__device__ float g_zf[(size_t)N_NODES * 256];       // fp32 z scratch
__device__ char  g_w1q[LAYERS * 2 * 256 * 128];     // [l][p][n=256][k=128]
__device__ float g_sw1[LAYERS * 256];
__device__ char  g_w2q[LAYERS * 2 * 128 * 256];     // [l][p][n=128][k=256]
__device__ float g_sw2[LAYERS * 128];
__device__ int g_rowptr[N_NODES + 1];
__device__ int g_cnt[N_NODES];
__device__ int g_cursor[N_NODES];
__device__ int g_srcs[EDGES];
__device__ int g_part[NSCAN];
__device__ int g_parts[NSCAN];

// ---------------- helpers -------------------------------------------------------
__device__ __forceinline__ uint32_t smem_u32(const void* p) {
    uint32_t a;
    asm("{ .reg .u64 t; cvta.to.shared.u64 t, %1; cvt.u32.u64 %0, t; }" : "=r"(a) : "l"(p));
    return a;
}

#define LDSM_X4(r0, r1, r2, r3, addr) \
    asm volatile("ldmatrix.sync.aligned.m8n8.x4.shared.b16 {%0,%1,%2,%3}, [%4];" \
        : "=r"(r0), "=r"(r1), "=r"(r2), "=r"(r3) : "r"(addr))

__device__ __forceinline__ void mma_s8(int* c, uint32_t a0, uint32_t a1, uint32_t a2,
                                       uint32_t a3, uint32_t b0, uint32_t b1) {
    asm volatile("mma.sync.aligned.m16n8k32.row.col.s32.s8.s8.s32 "
        "{%0,%1,%2,%3}, {%4,%5,%6,%7}, {%8,%9}, {%0,%1,%2,%3};"
        : "+r"(c[0]), "+r"(c[1]), "+r"(c[2]), "+r"(c[3])
        : "r"(a0), "r"(a1), "r"(a2), "r"(a3), "r"(b0), "r"(b1));
}

__device__ __forceinline__ void cp16(uint32_t dst, const void* src, uint32_t srcsz) {
    asm volatile("cp.async.ca.shared.global [%0], [%1], 16, %2;"
                 :: "r"(dst), "l"(src), "r"(srcsz) : "memory");
}
#define CP_COMMIT() asm volatile("cp.async.commit_group;" ::: "memory")
#define CP_WAIT0()  asm volatile("cp.async.wait_group 0;" ::: "memory")

__device__ __forceinline__ int qrn(float x) { return __float2int_rn(x); }
__device__ __forceinline__ int qcl(int x) { return max(-127, min(127, x)); }
__device__ __forceinline__ uint32_t pack8(int a, int b, int c, int d) {
    return (uint32_t)(a & 255) | ((uint32_t)(b & 255) << 8) |
           ((uint32_t)(c & 255) << 16) | ((uint32_t)(d & 255) << 24);
}

// ---------------- CSR build ------------------------------------------------------
__global__ void k_zero() {
    int i = blockIdx.x * blockDim.x + threadIdx.x;
    if (i < N_NODES) { g_cnt[i] = 0; g_cursor[i] = 0; }
}
__global__ void k_hist(const int* __restrict__ dst) {
    int e = blockIdx.x * blockDim.x + threadIdx.x;
    if (e < EDGES) atomicAdd(&g_cnt[dst[e]], 1);
}
__global__ void k_scan_a() {
    __shared__ int s[1024];
    int t = threadIdx.x, b = blockIdx.x;
    int i = b * 1024 + t;
    int v = (i < N_NODES) ? g_cnt[i] : 0;
    s[t] = v;
    __syncthreads();
    #pragma unroll
    for (int off = 1; off < 1024; off <<= 1) {
        int u = (t >= off) ? s[t - off] : 0;
        __syncthreads();
        s[t] += u;
        __syncthreads();
    }
    if (i < N_NODES) g_rowptr[i + 1] = s[t];
    if (t == 1023) g_part[b] = s[t];
}
__global__ void k_scan_b() {
    if (threadIdx.x == 0) {
        int acc = 0;
        for (int b = 0; b < NSCAN; b++) { g_parts[b] = acc; acc += g_part[b]; }
    }
}
__global__ void k_scan_c() {
    int t = threadIdx.x, b = blockIdx.x;
    int i = b * 1024 + t;
    if (i < N_NODES) g_rowptr[i + 1] += g_parts[b];
    if (i == 0) g_rowptr[0] = 0;
}
__global__ void k_fill(const int* __restrict__ src, const int* __restrict__ dst) {
    int e = blockIdx.x * blockDim.x + threadIdx.x;
    if (e < EDGES) {
        int d = dst[e];
        int p = g_rowptr[d] + atomicAdd(&g_cursor[d], 1);
        g_srcs[p] = src[e];
    }
}

// ---------------- W -> 2-digit int8, transposed [n][k] ---------------------------
__global__ void k_wconv(const float* __restrict__ W1, const float* __restrict__ W2) {
    int i = blockIdx.x * blockDim.x + threadIdx.x;
    if (i < LAYERS * 256) {
        int l = i >> 8, n = i & 255;
        float m = 0.f;
        for (int k = 0; k < 128; k++) m = fmaxf(m, fabsf(W1[(l * 128 + k) * 256 + n]));
        float s = (m > 0.f) ? m / 127.f : 1.f;
        float inv = (m > 0.f) ? 127.f / m : 0.f;
        char* p0 = g_w1q + ((size_t)(l * 2) * 256 + n) * 128;
        char* p1 = g_w1q + ((size_t)(l * 2 + 1) * 256 + n) * 128;
        for (int k = 0; k < 128; k++) {
            float w = W1[(l * 128 + k) * 256 + n];
            int q1 = qrn(w * inv);
            int q2 = qcl(qrn((w - q1 * s) * (256.f / s)));
            p0[k] = (char)q1; p1[k] = (char)q2;
        }
        g_sw1[i] = s;
    } else if (i < LAYERS * 256 + LAYERS * 128) {
        int j = i - LAYERS * 256;
        int l = j >> 7, n = j & 127;
        float m = 0.f;
        for (int k = 0; k < 256; k++) m = fmaxf(m, fabsf(W2[(l * 256 + k) * 128 + n]));
        float s = (m > 0.f) ? m / 127.f : 1.f;
        float inv = (m > 0.f) ? 127.f / m : 0.f;
        char* p0 = g_w2q + ((size_t)(l * 2) * 128 + n) * 256;
        char* p1 = g_w2q + ((size_t)(l * 2 + 1) * 128 + n) * 256;
        for (int k = 0; k < 256; k++) {
            float w = W2[(l * 256 + k) * 128 + n];
            int q1 = qrn(w * inv);
            int q2 = qcl(qrn((w - q1 * s) * (256.f / s)));
            p0[k] = (char)q1; p1[k] = (char)q2;
        }
        g_sw2[j] = s;
    }
}

// ---------------- aggregation + quantize: agg = h_i + sum h_j --------------------
__global__ void k_aggregate(const float* __restrict__ h) {
    int gw = (blockIdx.x * blockDim.x + threadIdx.x) >> 5;
    int lane = threadIdx.x & 31;
    if (gw >= N_NODES) return;
    const float4* hv = (const float4*)h;
    float4 acc = __ldg(&hv[(size_t)gw * 32 + lane]);
    int e0 = g_rowptr[gw], e1 = g_rowptr[gw + 1];
    for (int e = e0; e < e1; e++) {
        int j = g_srcs[e];
        float4 v = __ldg(&hv[(size_t)j * 32 + lane]);
        acc.x += v.x; acc.y += v.y; acc.z += v.z; acc.w += v.w;
    }
    float m = fmaxf(fmaxf(fabsf(acc.x), fabsf(acc.y)), fmaxf(fabsf(acc.z), fabsf(acc.w)));
    #pragma unroll
    for (int off = 16; off > 0; off >>= 1) m = fmaxf(m, __shfl_xor_sync(0xffffffffu, m, off));
    float s = (m > 0.f) ? m / 127.f : 1.f;
    float inv = (m > 0.f) ? 127.f / m : 0.f;
    float r256 = 256.f / s;
    int a1x = qrn(acc.x * inv), a1y = qrn(acc.y * inv), a1z = qrn(acc.z * inv), a1w = qrn(acc.w * inv);
    int a2x = qcl(qrn((acc.x - a1x * s) * r256));
    int a2y = qcl(qrn((acc.y - a1y * s) * r256));
    int a2z = qcl(qrn((acc.z - a1z * s) * r256));
    int a2w = qcl(qrn((acc.w - a1w * s) * r256));
    ((uint32_t*)g_a8)[(size_t)gw * 32 + lane] = pack8(a1x, a1y, a1z, a1w);
    ((uint32_t*)(g_a8 + (size_t)N_NODES * 128))[(size_t)gw * 32 + lane] = pack8(a2x, a2y, a2z, a2w);
    if (lane == 0) g_sa[gw] = s;
}

// ---------------- quantize z rows (fp32 -> 2-digit int8) -------------------------
__global__ void k_qz() {
    int row = blockIdx.x * 8 + (threadIdx.x >> 5);
    int lane = threadIdx.x & 31;
    if (row >= N_NODES) return;
    const float4* zf = (const float4*)g_zf;
    float4 a = zf[(size_t)row * 64 + lane];
    float4 b = zf[(size_t)row * 64 + 32 + lane];
    float m = fmaxf(fmaxf(fmaxf(fabsf(a.x), fabsf(a.y)), fmaxf(fabsf(a.z), fabsf(a.w))),
                    fmaxf(fmaxf(fabsf(b.x), fabsf(b.y)), fmaxf(fabsf(b.z), fabsf(b.w))));
    #pragma unroll
    for (int off = 16; off > 0; off >>= 1) m = fmaxf(m, __shfl_xor_sync(0xffffffffu, m, off));
    float s = (m > 0.f) ? m / 127.f : 1.f;
    float inv = (m > 0.f) ? 127.f / m : 0.f;
    float r256 = 256.f / s;
    int q1[8], q2[8];
    float v[8] = {a.x, a.y, a.z, a.w, b.x, b.y, b.z, b.w};
    #pragma unroll
    for (int t = 0; t < 8; t++) {
        q1[t] = qrn(v[t] * inv);
        q2[t] = qcl(qrn((v[t] - q1[t] * s) * r256));
    }
    uint32_t* z0 = (uint32_t*)g_z8;
    uint32_t* z1 = (uint32_t*)(g_z8 + (size_t)N_NODES * 256);
    z0[(size_t)row * 64 + lane]      = pack8(q1[0], q1[1], q1[2], q1[3]);
    z0[(size_t)row * 64 + 32 + lane] = pack8(q1[4], q1[5], q1[6], q1[7]);
    z1[(size_t)row * 64 + lane]      = pack8(q2[0], q2[1], q2[2], q2[3]);
    z1[(size_t)row * 64 + 32 + lane] = pack8(q2[4], q2[5], q2[6], q2[7]);
    if (lane == 0) g_sz[row] = s;
}

// ---------------- SMEM layouts ----------------------------------------------------
// GEMM1: W [2][256][144], A [2][128][144], alpha[256], beta[256]
#define G1_W     0
#define G1_WP    36864
#define G1_A     73728
#define G1_AP    18432
#define G1_ALPHA 110592
#define G1_BETA  111616
#define SMEM1    112640
// GEMM2: W [2][128][272], A [2][128][272], alpha[128], beta[128]
#define G2_W     0
#define G2_WP    34816
#define G2_A     69632
#define G2_ALPHA 139264
#define G2_BETA  139776
#define SMEM2    140288

__device__ __forceinline__ void g1_issue(uint32_t sb, int tid, int row0) {
    int p = tid >> 8, t = tid & 255;
    int r = t >> 1, c = t & 1;
    int gr = row0 + r;
    uint32_t pr = (gr < N_NODES) ? 16u : 0u;
    const char* src = g_a8 + (size_t)p * N_NODES * 128 + (size_t)gr * 128 + c * 64;
    uint32_t dst = sb + G1_A + p * G1_AP + r * 144 + c * 64;
    #pragma unroll
    for (int s = 0; s < 4; s++) cp16(dst + s * 16, src + s * 16, pr);
    CP_COMMIT();
}
__device__ __forceinline__ void g2_issue(uint32_t sb, int tid, int row0) {
    int p = tid >> 8, t = tid & 255;
    int r = t >> 1, c = t & 1;
    int gr = row0 + r;
    uint32_t pr = (gr < N_NODES) ? 16u : 0u;
    const char* src = g_z8 + (size_t)p * N_NODES * 256 + (size_t)gr * 256 + c * 128;
    uint32_t dst = sb + G2_A + p * G2_WP + r * 272 + c * 128;
    #pragma unroll
    for (int s = 0; s < 8; s++) cp16(dst + s * 16, src + s * 16, pr);
    CP_COMMIT();
}

// ---------------- GEMM1: zf = relu(BN1(agg @ W1 + b1)),  [N,128]x[128,256] -------
// 512 thr, 16 warps 4x4; warp tile m32 x n32; two n-half passes per tile
__global__ void __launch_bounds__(512, 1) k_gemm1(
    int layer, const float* __restrict__ bias,
    const float* __restrict__ bn_g, const float* __restrict__ bn_b,
    const float* __restrict__ bn_m, const float* __restrict__ bn_v)
{
    extern __shared__ char sm[];
    uint32_t sb = smem_u32(sm);
    int tid = threadIdx.x, lane = tid & 31, wid = tid >> 5;

    g1_issue(sb, tid, blockIdx.x << 7);

    {   // W: gmem [p][n][128] -> smem [p][n][144]
        const uint4* s = (const uint4*)(g_w1q + (size_t)layer * 2 * 256 * 128);
        #pragma unroll 2
        for (int i = tid; i < 4096; i += 512) {
            int p = i >> 11, n = (i >> 3) & 255, c = i & 7;
            *(uint4*)(sm + G1_W + p * G1_WP + n * 144 + c * 16) = s[i];
        }
    }
    float* sAl = (float*)(sm + G1_ALPHA);
    float* sBe = (float*)(sm + G1_BETA);
    if (tid < 256) {
        float al = bn_g[tid] * rsqrtf(bn_v[tid] + BN_EPS);
        sAl[tid] = al * g_sw1[layer * 256 + tid];
        sBe[tid] = (bias[tid] - bn_m[tid]) * al + bn_b[tid];
    }
    __syncthreads();

    int m0 = (wid >> 2) * 32;
    int l7 = lane & 7, l34 = (lane >> 3) & 1, l4 = lane >> 4;
    uint32_t aA = sb + G1_A + (m0 + l7 + l34 * 8) * 144 + l4 * 16;
    uint32_t aB = sb + G1_W + (((wid & 3) * 32) + l7 + l4 * 8) * 144 + l34 * 16;
    int q = lane & 3;

    for (int tile = blockIdx.x; tile < NT; tile += gridDim.x) {
        int row0 = tile << 7;
        CP_WAIT0();
        __syncthreads();

        #pragma unroll 1
        for (int np = 0; np < 2; np++) {
            uint32_t npo = (uint32_t)np * (128 * 144);
            int c1[2][4][4], c2[2][4][4];
            #pragma unroll
            for (int i = 0; i < 2; i++)
                #pragma unroll
                for (int j = 0; j < 4; j++)
                    #pragma unroll
                    for (int f = 0; f < 4; f++) { c1[i][j][f] = 0; c2[i][j][f] = 0; }

            #pragma unroll
            for (int ks = 0; ks < 4; ks++) {
                uint32_t kb = ks << 5;
                uint32_t A1[2][4], A2[2][4], B1[2][4], B2[2][4];
                #pragma unroll
                for (int i = 0; i < 2; i++) {
                    LDSM_X4(A1[i][0], A1[i][1], A1[i][2], A1[i][3], aA + i * 2304 + kb);
                    LDSM_X4(A2[i][0], A2[i][1], A2[i][2], A2[i][3], aA + G1_AP + i * 2304 + kb);
                }
                #pragma unroll
                for (int jj = 0; jj < 2; jj++) {
                    LDSM_X4(B1[jj][0], B1[jj][1], B1[jj][2], B1[jj][3], aB + npo + jj * 2304 + kb);
                    LDSM_X4(B2[jj][0], B2[jj][1], B2[jj][2], B2[jj][3], aB + G1_WP + npo + jj * 2304 + kb);
                }
                #pragma unroll
                for (int i = 0; i < 2; i++)
                    #pragma unroll
                    for (int j = 0; j < 4; j++)
                        mma_s8(c1[i][j], A1[i][0], A1[i][1], A1[i][2], A1[i][3],
                               B1[j >> 1][(j & 1) * 2], B1[j >> 1][(j & 1) * 2 + 1]);
                #pragma unroll
                for (int i = 0; i < 2; i++)
                    #pragma unroll
                    for (int j = 0; j < 4; j++)
                        mma_s8(c2[i][j], A1[i][0], A1[i][1], A1[i][2], A1[i][3],
                               B2[j >> 1][(j & 1) * 2], B2[j >> 1][(j & 1) * 2 + 1]);
                #pragma unroll
                for (int i = 0; i < 2; i++)
                    #pragma unroll
                    for (int j = 0; j < 4; j++)
                        mma_s8(c2[i][j], A2[i][0], A2[i][1], A2[i][2], A2[i][3],
                               B1[j >> 1][(j & 1) * 2], B1[j >> 1][(j & 1) * 2 + 1]);
            }

            if (np == 1) {   // A fully consumed; prefetch next tile
                __syncthreads();
                g1_issue(sb, tid, (tile + gridDim.x) << 7);
            }

            int nb = (wid & 3) * 32 + np * 128;
            #pragma unroll
            for (int i = 0; i < 2; i++) {
                #pragma unroll
                for (int hf = 0; hf < 2; hf++) {
                    int r = row0 + m0 + i * 16 + (lane >> 2) + hf * 8;
                    if (r < N_NODES) {
                        float sa = __ldg(&g_sa[r]);
                        float* dst = g_zf + (size_t)r * 256;
                        #pragma unroll
                        for (int j = 0; j < 4; j++) {
                            int c = nb + j * 8 + 2 * q;
                            float v0 = (float)c1[i][j][hf*2]   + (float)c2[i][j][hf*2]   * 0.00390625f;
                            float v1 = (float)c1[i][j][hf*2+1] + (float)c2[i][j][hf*2+1] * 0.00390625f;
                            float y0 = fmaxf(fmaf(v0 * sa, sAl[c],     sBe[c]),     0.f);
                            float y1 = fmaxf(fmaf(v1 * sa, sAl[c + 1], sBe[c + 1]), 0.f);
                            *(float2*)(dst + c) = make_float2(y0, y1);
                        }
                    }
                }
            }
        }
        __syncthreads();   // epilogue reads of smem alpha/beta done before next overwrite cycle
    }
}

// ---------------- GEMM2: h = BN_o(z @ W2 + b2)(+relu),  [N,256]x[256,128] --------
// 512 thr, 16 warps 4x4; warp tile m32 x n32; K=256 = 8 ksteps
__global__ void __launch_bounds__(512, 1) k_gemm2(
    int layer, const float* __restrict__ bias,
    const float* __restrict__ bn_g, const float* __restrict__ bn_b,
    const float* __restrict__ bn_m, const float* __restrict__ bn_v,
    float* __restrict__ out, int relu)
{
    extern __shared__ char sm[];
    uint32_t sb = smem_u32(sm);
    int tid = threadIdx.x, lane = tid & 31, wid = tid >> 5;

    g2_issue(sb, tid, blockIdx.x << 7);

    {   // W2: gmem [p][n][256] -> smem [p][n][272]
        const uint4* s = (const uint4*)(g_w2q + (size_t)layer * 2 * 128 * 256);
        #pragma unroll 2
        for (int i = tid; i < 4096; i += 512) {
            int p = i >> 11, n = (i >> 4) & 127, c = i & 15;
            *(uint4*)(sm + G2_W + p * G2_WP + n * 272 + c * 16) = s[i];
        }
    }
    float* sAl = (float*)(sm + G2_ALPHA);
    float* sBe = (float*)(sm + G2_BETA);
    if (tid < 128) {
        float al = bn_g[tid] * rsqrtf(bn_v[tid] + BN_EPS);
        sAl[tid] = al * g_sw2[layer * 128 + tid];
        sBe[tid] = (bias[tid] - bn_m[tid]) * al + bn_b[tid];
    }
    __syncthreads();

    int m0 = (wid >> 2) * 32, nb = (wid & 3) * 32;
    int l7 = lane & 7, l34 = (lane >> 3) & 1, l4 = lane >> 4;
    uint32_t aA = sb + G2_A + (m0 + l7 + l34 * 8) * 272 + l4 * 16;
    uint32_t aB = sb + G2_W + (nb + l7 + l4 * 8) * 272 + l34 * 16;
    int q = lane & 3;

    for (int tile = blockIdx.x; tile < NT; tile += gridDim.x) {
        int row0 = tile << 7;
        CP_WAIT0();
        __syncthreads();

        int c1[2][4][4], c2[2][4][4];
        #pragma unroll
        for (int i = 0; i < 2; i++)
            #pragma unroll
            for (int j = 0; j < 4; j++)
                #pragma unroll
                for (int f = 0; f < 4; f++) { c1[i][j][f] = 0; c2[i][j][f] = 0; }

        #pragma unroll 2
        for (int ks = 0; ks < 8; ks++) {
            uint32_t kb = ks << 5;
            uint32_t A1[2][4], A2[2][4], B1[2][4], B2[2][4];
            #pragma unroll
            for (int i = 0; i < 2; i++) {
                LDSM_X4(A1[i][0], A1[i][1], A1[i][2], A1[i][3], aA + i * 4352 + kb);
                LDSM_X4(A2[i][0], A2[i][1], A2[i][2], A2[i][3], aA + G2_WP + i * 4352 + kb);
            }
            #pragma unroll
            for (int jj = 0; jj < 2; jj++) {
                LDSM_X4(B1[jj][0], B1[jj][1], B1[jj][2], B1[jj][3], aB + jj * 4352 + kb);
                LDSM_X4(B2[jj][0], B2[jj][1], B2[jj][2], B2[jj][3], aB + G2_WP + jj * 4352 + kb);
            }
            #pragma unroll
            for (int i = 0; i < 2; i++)
                #pragma unroll
                for (int j = 0; j < 4; j++)
                    mma_s8(c1[i][j], A1[i][0], A1[i][1], A1[i][2], A1[i][3],
                           B1[j >> 1][(j & 1) * 2], B1[j >> 1][(j & 1) * 2 + 1]);
            #pragma unroll
            for (int i = 0; i < 2; i++)
                #pragma unroll
                for (int j = 0; j < 4; j++)
                    mma_s8(c2[i][j], A1[i][0], A1[i][1], A1[i][2], A1[i][3],
                           B2[j >> 1][(j & 1) * 2], B2[j >> 1][(j & 1) * 2 + 1]);
            #pragma unroll
            for (int i = 0; i < 2; i++)
                #pragma unroll
                for (int j = 0; j < 4; j++)
                    mma_s8(c2[i][j], A2[i][0], A2[i][1], A2[i][2], A2[i][3],
                           B1[j >> 1][(j & 1) * 2], B1[j >> 1][(j & 1) * 2 + 1]);
        }

        __syncthreads();
        g2_issue(sb, tid, (tile + gridDim.x) << 7);

        #pragma unroll
        for (int i = 0; i < 2; i++) {
            #pragma unroll
            for (int hf = 0; hf < 2; hf++) {
                int r = row0 + m0 + i * 16 + (lane >> 2) + hf * 8;
                if (r < N_NODES) {
                    float sz = __ldg(&g_sz[r]);
                    float* dst = out + (size_t)r * 128;
                    #pragma unroll
                    for (int j = 0; j < 4; j++) {
                        int c = nb + j * 8 + 2 * q;
                        float v0 = (float)c1[i][j][hf*2]   + (float)c2[i][j][hf*2]   * 0.00390625f;
                        float v1 = (float)c1[i][j][hf*2+1] + (float)c2[i][j][hf*2+1] * 0.00390625f;
                        float y0 = fmaf(v0 * sz, sAl[c],     sBe[c]);
                        float y1 = fmaf(v1 * sz, sAl[c + 1], sBe[c + 1]);
                        if (relu) { y0 = fmaxf(y0, 0.f); y1 = fmaxf(y1, 0.f); }
                        *(float2*)(dst + c) = make_float2(y0, y1);
                    }
                }
            }
        }
        __syncthreads();
    }
}

// ---------------- launch ----------------------------------------------------------
extern "C" void kernel_launch(void* const* d_in, const int* in_sizes, int n_in,
                              void* d_out, int out_size) {
    const float* x     = (const float*)d_in[0];
    const int*   ei    = (const int*)d_in[1];
    const float* W1    = (const float*)d_in[2];
    const float* b1    = (const float*)d_in[3];
    const float* bn1_g = (const float*)d_in[4];
    const float* bn1_b = (const float*)d_in[5];
    const float* bn1_m = (const float*)d_in[6];
    const float* bn1_v = (const float*)d_in[7];
    const float* W2    = (const float*)d_in[8];
    const float* b2    = (const float*)d_in[9];
    const float* bno_g = (const float*)d_in[10];
    const float* bno_b = (const float*)d_in[11];
    const float* bno_m = (const float*)d_in[12];
    const float* bno_v = (const float*)d_in[13];
    float* out = (float*)d_out;

    cudaFuncSetAttribute(k_gemm1, cudaFuncAttributeMaxDynamicSharedMemorySize, SMEM1);
    cudaFuncSetAttribute(k_gemm2, cudaFuncAttributeMaxDynamicSharedMemorySize, SMEM2);

    const int* src = ei;
    const int* dst = ei + EDGES;

    k_wconv<<<(LAYERS * 384 + 255) / 256, 256>>>(W1, W2);
    k_zero<<<(N_NODES + 255) / 256, 256>>>();
    k_hist<<<(EDGES + 255) / 256, 256>>>(dst);
    k_scan_a<<<NSCAN, 1024>>>();
    k_scan_b<<<1, 32>>>();
    k_scan_c<<<NSCAN, 1024>>>();
    k_fill<<<(EDGES + 255) / 256, 256>>>(src, dst);

    const float* h = x;
    for (int l = 0; l < LAYERS; l++) {
        k_aggregate<<<(N_NODES * 32 + 255) / 256, 256>>>(h);
        k_gemm1<<<GRID_G, 512, SMEM1>>>(l, b1 + (size_t)l * 256,
                bn1_g + (size_t)l * 256, bn1_b + (size_t)l * 256,
                bn1_m + (size_t)l * 256, bn1_v + (size_t)l * 256);
        k_qz<<<(N_NODES + 7) / 8, 256>>>();
        k_gemm2<<<GRID_G, 512, SMEM2>>>(l, b2 + (size_t)l * 128,
                bno_g + (size_t)l * 128, bno_b + (size_t)l * 128,
                bno_m + (size_t)l * 128, bno_v + (size_t)l * 128,
                out, (l != LAYERS - 1) ? 1 : 0);
        h = out;
    }
}

// round 8
// speedup vs baseline: 1.7077x; 1.7077x over previous
#include <cuda_runtime.h>
#include <cuda_bf16.h>
#include <cstdint>

#define N_NODES 100000
#define EDGES   640000
#define LAYERS  5
#define BN_EPS  1e-5f
#define NT1     1563         // ceil(100000/64)   (gemm1 M-tile 64)
#define NT2     782          // ceil(100000/128)  (gemm2 M-tile 128)
#define GRID_G  148
#define NSCAN   98

// ---------------- static scratch ------------------------------------------------
__device__ __nv_bfloat16 g_z_hi[(size_t)N_NODES * 256];
__device__ __nv_bfloat16 g_z_lo[(size_t)N_NODES * 256];
__device__ __nv_bfloat16 g_w1t[LAYERS * 2 * 32768];   // [l][term][n=256][k=128]
__device__ __nv_bfloat16 g_w2t[LAYERS * 2 * 32768];   // [l][term][n=128][k=256]
__device__ int g_rowptr[N_NODES + 1];
__device__ int g_cnt[N_NODES];
__device__ int g_cursor[N_NODES];
__device__ int g_srcs[EDGES];
__device__ int g_part[NSCAN];

// ---------------- helpers -------------------------------------------------------
__device__ __forceinline__ uint32_t smem_u32(const void* p) {
    uint32_t a;
    asm("{ .reg .u64 t; cvta.to.shared.u64 t, %1; cvt.u32.u64 %0, t; }" : "=r"(a) : "l"(p));
    return a;
}
__device__ __forceinline__ uint32_t pack_bf(__nv_bfloat16 a, __nv_bfloat16 b) {
    return ((uint32_t)__bfloat16_as_ushort(b) << 16) | (uint32_t)__bfloat16_as_ushort(a);
}
__device__ __forceinline__ void split_bf(float x, __nv_bfloat16& h, __nv_bfloat16& l) {
    h = __float2bfloat16(x);
    l = __float2bfloat16(x - __bfloat162float(h));
}

#define LDSM_X4(r0, r1, r2, r3, addr) \
    asm volatile("ldmatrix.sync.aligned.m8n8.x4.shared.b16 {%0,%1,%2,%3}, [%4];" \
        : "=r"(r0), "=r"(r1), "=r"(r2), "=r"(r3) : "r"(addr))

__device__ __forceinline__ void mma_bf16(float& c0, float& c1, float& c2, float& c3,
        uint32_t a0, uint32_t a1, uint32_t a2, uint32_t a3, uint32_t b0, uint32_t b1) {
    asm volatile("mma.sync.aligned.m16n8k16.row.col.f32.bf16.bf16.f32 "
        "{%0,%1,%2,%3}, {%4,%5,%6,%7}, {%8,%9}, {%0,%1,%2,%3};"
        : "+f"(c0), "+f"(c1), "+f"(c2), "+f"(c3)
        : "r"(a0), "r"(a1), "r"(a2), "r"(a3), "r"(b0), "r"(b1));
}

__device__ __forceinline__ void cp16(uint32_t dst, const void* src, uint32_t srcsz) {
    asm volatile("cp.async.ca.shared.global [%0], [%1], 16, %2;"
                 :: "r"(dst), "l"(src), "r"(srcsz) : "memory");
}
#define CP_COMMIT() asm volatile("cp.async.commit_group;" ::: "memory")
__device__ __forceinline__ void cp_wait_dyn(int n) {
    switch (n) {
        case 0: asm volatile("cp.async.wait_group 0;" ::: "memory"); break;
        case 2: asm volatile("cp.async.wait_group 2;" ::: "memory"); break;
        case 4: asm volatile("cp.async.wait_group 4;" ::: "memory"); break;
        case 6: asm volatile("cp.async.wait_group 6;" ::: "memory"); break;
        default: asm volatile("cp.async.wait_group 0;" ::: "memory"); break;
    }
}

// ---------------- prep: W split-bf16 transpose + CSR zero (fused) ----------------
__global__ void k_prep(const float* __restrict__ W1, const float* __restrict__ W2) {
    int i = blockIdx.x * blockDim.x + threadIdx.x;
    const int TOT = LAYERS * 32768;
    if (i < N_NODES) { g_cnt[i] = 0; g_cursor[i] = 0; }
    if (i < TOT) {
        int l = i >> 15, r = i & 32767;
        int k = r >> 8, n = r & 255;           // W1[l][k][n]
        __nv_bfloat16 hi, lo;
        split_bf(W1[i], hi, lo);
        g_w1t[(size_t)l * 65536 + n * 128 + k] = hi;
        g_w1t[(size_t)l * 65536 + 32768 + n * 128 + k] = lo;
    } else if (i < 2 * TOT) {
        int j = i - TOT;
        int l = j >> 15, r = j & 32767;
        int k = r >> 7, n = r & 127;           // W2[l][k][n]
        __nv_bfloat16 hi, lo;
        split_bf(W2[j], hi, lo);
        g_w2t[(size_t)l * 65536 + n * 256 + k] = hi;
        g_w2t[(size_t)l * 65536 + 32768 + n * 256 + k] = lo;
    }
}

// ---------------- CSR build ------------------------------------------------------
__global__ void k_hist(const int* __restrict__ dst) {
    int e = blockIdx.x * blockDim.x + threadIdx.x;
    if (e < EDGES) atomicAdd(&g_cnt[dst[e]], 1);
}
__global__ void k_scan_a() {
    __shared__ int s[1024];
    int t = threadIdx.x, b = blockIdx.x;
    int i = b * 1024 + t;
    int v = (i < N_NODES) ? g_cnt[i] : 0;
    s[t] = v;
    __syncthreads();
    #pragma unroll
    for (int off = 1; off < 1024; off <<= 1) {
        int u = (t >= off) ? s[t - off] : 0;
        __syncthreads();
        s[t] += u;
        __syncthreads();
    }
    if (i < N_NODES) g_rowptr[i + 1] = s[t];
    if (t == 1023) g_part[b] = s[t];
}
__global__ void k_scan_c() {
    __shared__ int pre;
    int t = threadIdx.x, b = blockIdx.x;
    if (t == 0) {
        int acc = 0;
        for (int j = 0; j < b; j++) acc += g_part[j];
        pre = acc;
    }
    __syncthreads();
    int i = b * 1024 + t;
    if (i < N_NODES) g_rowptr[i + 1] += pre;
    if (i == 0) g_rowptr[0] = 0;
}
__global__ void k_fill(const int* __restrict__ src, const int* __restrict__ dst) {
    int e = blockIdx.x * blockDim.x + threadIdx.x;
    if (e < EDGES) {
        int d = dst[e];
        int p = g_rowptr[d] + atomicAdd(&g_cursor[d], 1);
        g_srcs[p] = src[e];
    }
}

// ---------------- SMEM layout: GEMM1 (fused aggregation) -------------------------
#define STR1B    272
#define G1_ALPHA 0
#define G1_BETA  1024
#define G1_W     2048
#define G1_WLOFF 69632
#define G1_A     141312
#define G1_BUF   34816
#define G1_LO    17408
#define SMEM1    210944
// GEMM2: as R5
#define STR2B    528
#define G2_W     0
#define G2_WL    67584
#define G2_ZH    135168
#define G2_ZL    169984
#define G2_ALPHA 204800
#define G2_BETA  205312
#define SMEM2    205824

// producer gather: 8 warps x 8 rows; agg = h[gr] + sum h[src]; split-bf16 to smem
__device__ __forceinline__ void gather_tile(char* sm, const float* __restrict__ h,
                                            int pw, int lane, int row0, uint32_t bufoff) {
    const float4* hv = (const float4*)h;
    #pragma unroll 1
    for (int j = 0; j < 8; j++) {
        int rl = pw * 8 + j;
        int gr = row0 + rl;
        float4 acc = make_float4(0.f, 0.f, 0.f, 0.f);
        if (gr < N_NODES) {
            acc = __ldg(&hv[(size_t)gr * 32 + lane]);
            int e0 = g_rowptr[gr], e1 = g_rowptr[gr + 1];
            for (int e = e0; e < e1; e++) {
                int s = g_srcs[e];
                float4 v = __ldg(&hv[(size_t)s * 32 + lane]);
                acc.x += v.x; acc.y += v.y; acc.z += v.z; acc.w += v.w;
            }
        }
        __nv_bfloat16 h0, h1, h2, h3, l0, l1, l2, l3;
        split_bf(acc.x, h0, l0); split_bf(acc.y, h1, l1);
        split_bf(acc.z, h2, l2); split_bf(acc.w, h3, l3);
        uint2 ph, pl;
        ph.x = pack_bf(h0, h1); ph.y = pack_bf(h2, h3);
        pl.x = pack_bf(l0, l1); pl.y = pack_bf(l2, l3);
        *(uint2*)(sm + bufoff + rl * STR1B + lane * 8) = ph;
        *(uint2*)(sm + bufoff + G1_LO + rl * STR1B + lane * 8) = pl;
    }
}

// ---------------- GEMM1 (fused agg): z = relu(BN1((h_i+sum h_j) @ W1 + b1)) ------
// 512 thr: warps 0-7 consumers (MMA, m-tile 64: 2x4 warp grid m32 x n64),
//          warps 8-15 producers (gather next tile)
__global__ void __launch_bounds__(512, 1) k_gemm1(
    int layer, const float* __restrict__ h, const float* __restrict__ bias,
    const float* __restrict__ bn_g, const float* __restrict__ bn_b,
    const float* __restrict__ bn_m, const float* __restrict__ bn_v)
{
    extern __shared__ char sm[];
    uint32_t sb = smem_u32(sm);
    int tid = threadIdx.x, lane = tid & 31, wid = tid >> 5;

    {   // W hi+lo into padded smem [n=256][k=128]
        const uint4* s = (const uint4*)(g_w1t + (size_t)layer * 65536);
        #pragma unroll 2
        for (int i = tid; i < 4096; i += 512) {
            int r = i >> 4, c = i & 15;
            *(uint4*)(sm + G1_W + r * STR1B + c * 16) = s[i];
            *(uint4*)(sm + G1_W + G1_WLOFF + r * STR1B + c * 16) = s[i + 4096];
        }
    }
    float* sAl = (float*)(sm + G1_ALPHA);
    float* sBe = (float*)(sm + G1_BETA);
    if (tid < 256) {
        float s = bn_g[tid] * rsqrtf(bn_v[tid] + BN_EPS);
        sAl[tid] = s;
        sBe[tid] = (bias[tid] - bn_m[tid]) * s + bn_b[tid];
    }

    // prologue: producers gather first tile into buf0
    if (wid >= 8) gather_tile(sm, h, wid - 8, lane, blockIdx.x << 6, G1_A);
    __syncthreads();

    int m0 = ((wid >> 2) & 1) * 32, n0 = (wid & 3) * 64;
    uint32_t aoffA = (uint32_t)((m0 + (lane & 15)) * STR1B + ((lane >> 4) << 4));
    uint32_t boff = (uint32_t)((n0 + ((lane >> 4) << 3) + (lane & 7)) * STR1B + (((lane >> 3) & 1) << 4));
    uint32_t aWH = sb + G1_W + boff;
    uint32_t aWL = sb + G1_W + G1_WLOFF + boff;
    int q = lane & 3;

    int cur = 0;
    for (int tile = blockIdx.x; tile < NT1; tile += gridDim.x) {
        int row0 = tile << 6;
        if (wid >= 8) {
            int nxt = tile + gridDim.x;
            if (nxt < NT1)
                gather_tile(sm, h, wid - 8, lane, nxt << 6, G1_A + (cur ^ 1) * G1_BUF);
        } else {
            uint32_t aAH = sb + G1_A + cur * G1_BUF + aoffA;
            uint32_t aAL = aAH + G1_LO;

            float acc[2][8][4];
            #pragma unroll
            for (int i = 0; i < 2; i++)
                #pragma unroll
                for (int j = 0; j < 8; j++)
                    #pragma unroll
                    for (int f = 0; f < 4; f++) acc[i][j][f] = 0.f;

            #pragma unroll 2
            for (int ks = 0; ks < 8; ks++) {
                uint32_t kb = ks << 5;
                uint32_t Ah[2][4], Alr[2][4], B[4][4];
                #pragma unroll
                for (int i = 0; i < 2; i++) {
                    LDSM_X4(Ah[i][0], Ah[i][1], Ah[i][2], Ah[i][3], aAH + i * (16 * STR1B) + kb);
                    LDSM_X4(Alr[i][0], Alr[i][1], Alr[i][2], Alr[i][3], aAL + i * (16 * STR1B) + kb);
                }
                #pragma unroll
                for (int j2 = 0; j2 < 4; j2++)
                    LDSM_X4(B[j2][0], B[j2][1], B[j2][2], B[j2][3], aWH + j2 * (16 * STR1B) + kb);
                #pragma unroll
                for (int i = 0; i < 2; i++)
                    #pragma unroll
                    for (int j = 0; j < 8; j++)
                        mma_bf16(acc[i][j][0], acc[i][j][1], acc[i][j][2], acc[i][j][3],
                                 Ah[i][0], Ah[i][1], Ah[i][2], Ah[i][3],
                                 B[j >> 1][(j & 1) * 2], B[j >> 1][(j & 1) * 2 + 1]);
                #pragma unroll
                for (int i = 0; i < 2; i++)
                    #pragma unroll
                    for (int j = 0; j < 8; j++)
                        mma_bf16(acc[i][j][0], acc[i][j][1], acc[i][j][2], acc[i][j][3],
                                 Alr[i][0], Alr[i][1], Alr[i][2], Alr[i][3],
                                 B[j >> 1][(j & 1) * 2], B[j >> 1][(j & 1) * 2 + 1]);
                #pragma unroll
                for (int j2 = 0; j2 < 4; j2++)
                    LDSM_X4(B[j2][0], B[j2][1], B[j2][2], B[j2][3], aWL + j2 * (16 * STR1B) + kb);
                #pragma unroll
                for (int i = 0; i < 2; i++)
                    #pragma unroll
                    for (int j = 0; j < 8; j++)
                        mma_bf16(acc[i][j][0], acc[i][j][1], acc[i][j][2], acc[i][j][3],
                                 Ah[i][0], Ah[i][1], Ah[i][2], Ah[i][3],
                                 B[j >> 1][(j & 1) * 2], B[j >> 1][(j & 1) * 2 + 1]);
            }

            // epilogue: BN + relu + split-bf16 store of z
            uint32_t* zh = (uint32_t*)g_z_hi;
            uint32_t* zl = (uint32_t*)g_z_lo;
            #pragma unroll
            for (int i = 0; i < 2; i++) {
                #pragma unroll
                for (int hf = 0; hf < 2; hf++) {
                    int r = row0 + m0 + i * 16 + (lane >> 2) + hf * 8;
                    if (r < N_NODES) {
                        size_t rb = (size_t)r * 128 + (n0 >> 1) + q;
                        #pragma unroll
                        for (int j = 0; j < 8; j++) {
                            int c = n0 + j * 8 + 2 * q;
                            float z0 = fmaxf(fmaf(acc[i][j][hf * 2],     sAl[c],     sBe[c]),     0.f);
                            float z1 = fmaxf(fmaf(acc[i][j][hf * 2 + 1], sAl[c + 1], sBe[c + 1]), 0.f);
                            __nv_bfloat16 h0, h1, l0, l1;
                            split_bf(z0, h0, l0); split_bf(z1, h1, l1);
                            zh[rb + j * 4] = pack_bf(h0, h1);
                            zl[rb + j * 4] = pack_bf(l0, l1);
                        }
                    }
                }
            }
        }
        __syncthreads();
        cur ^= 1;
    }
}

// ---- cp.async z-tile issuer for GEMM2 (R5-exact: 8 groups, group s == kstep s) ---
__device__ __forceinline__ void g2_issue_ch(uint32_t sb, int tid, int row0, int ch) {
    int hl = tid >> 8;
    int t = tid & 255;
    int r = t >> 1, c = t & 1;
    int gr = row0 + r;
    uint32_t p = (gr < N_NODES) ? 16u : 0u;
    const char* gsrc = (const char*)(hl ? g_z_lo : g_z_hi) + (size_t)gr * 512 + ch * 256 + c * 16;
    uint32_t dsm = sb + (hl ? G2_ZL : G2_ZH) + r * STR1B + c * 16;
    #pragma unroll
    for (int s = 0; s < 8; s++) {
        cp16(dsm + s * 32, gsrc + s * 32, p);
        CP_COMMIT();
    }
}

// ---------------- GEMM2: h = BN_o(z @ W2 + b2)(+relu),  [N,256]x[256,128] --------
// 512 threads, 16 warps 4x4; warp tile 32m x 32n; K=256 in 2 chunks (as R5)
__global__ void __launch_bounds__(512, 1) k_gemm2(
    int layer, const float* __restrict__ bias,
    const float* __restrict__ bn_g, const float* __restrict__ bn_b,
    const float* __restrict__ bn_m, const float* __restrict__ bn_v,
    float* __restrict__ out, int relu)
{
    extern __shared__ char sm[];
    uint32_t sb = smem_u32(sm);
    int tid = threadIdx.x, lane = tid & 31, wid = tid >> 5;

    g2_issue_ch(sb, tid, blockIdx.x << 7, 0);

    {
        const uint4* s = (const uint4*)(g_w2t + (size_t)layer * 65536);
        #pragma unroll 2
        for (int i = tid; i < 4096; i += 512) {
            int r = i >> 5, c = i & 31;
            *(uint4*)(sm + G2_W + r * STR2B + c * 16) = s[i];
            *(uint4*)(sm + G2_WL + r * STR2B + c * 16) = s[i + 4096];
        }
    }
    float* sAl = (float*)(sm + G2_ALPHA);
    float* sBe = (float*)(sm + G2_BETA);
    if (tid < 128) {
        float s = bn_g[tid] * rsqrtf(bn_v[tid] + BN_EPS);
        sAl[tid] = s;
        sBe[tid] = (bias[tid] - bn_m[tid]) * s + bn_b[tid];
    }
    __syncthreads();

    int m0 = (wid >> 2) * 32, nb = (wid & 3) * 32;
    uint32_t aoff = (uint32_t)((m0 + (lane & 15)) * STR1B + ((lane >> 4) << 4));
    uint32_t aZH = sb + G2_ZH + aoff;
    uint32_t aZL = sb + G2_ZL + aoff;
    uint32_t boff = (uint32_t)((nb + ((lane >> 4) << 3) + (lane & 7)) * STR2B + (((lane >> 3) & 1) << 4));
    uint32_t aWH = sb + G2_W + boff;
    uint32_t aWL = sb + G2_WL + boff;
    int q = lane & 3;

    for (int tile = blockIdx.x; tile < NT2; tile += gridDim.x) {
        int row0 = tile << 7;

        float acc[2][4][4];
        #pragma unroll
        for (int i = 0; i < 2; i++)
            #pragma unroll
            for (int j = 0; j < 4; j++)
                #pragma unroll
                for (int f = 0; f < 4; f++) acc[i][j][f] = 0.f;

        #pragma unroll 1
        for (int ch = 0; ch < 2; ch++) {
            uint32_t chb = (uint32_t)ch * 256;
            #pragma unroll
            for (int kp = 0; kp < 4; kp++) {
                cp_wait_dyn(6 - 2 * kp);
                __syncthreads();
                #pragma unroll
                for (int kq = 0; kq < 2; kq++) {
                    int ks = kp * 2 + kq;
                    uint32_t kb = ks << 5;
                    uint32_t Ah[2][4], Alr[2][4], B[2][4];
                    #pragma unroll
                    for (int i = 0; i < 2; i++) {
                        LDSM_X4(Ah[i][0], Ah[i][1], Ah[i][2], Ah[i][3], aZH + i * (16 * STR1B) + kb);
                        LDSM_X4(Alr[i][0], Alr[i][1], Alr[i][2], Alr[i][3], aZL + i * (16 * STR1B) + kb);
                    }
                    #pragma unroll
                    for (int jj = 0; jj < 2; jj++)
                        LDSM_X4(B[jj][0], B[jj][1], B[jj][2], B[jj][3],
                                aWH + jj * (16 * STR2B) + chb + kb);
                    #pragma unroll
                    for (int i = 0; i < 2; i++)
                        #pragma unroll
                        for (int j = 0; j < 4; j++)
                            mma_bf16(acc[i][j][0], acc[i][j][1], acc[i][j][2], acc[i][j][3],
                                     Ah[i][0], Ah[i][1], Ah[i][2], Ah[i][3],
                                     B[j >> 1][(j & 1) * 2], B[j >> 1][(j & 1) * 2 + 1]);
                    #pragma unroll
                    for (int i = 0; i < 2; i++)
                        #pragma unroll
                        for (int j = 0; j < 4; j++)
                            mma_bf16(acc[i][j][0], acc[i][j][1], acc[i][j][2], acc[i][j][3],
                                     Alr[i][0], Alr[i][1], Alr[i][2], Alr[i][3],
                                     B[j >> 1][(j & 1) * 2], B[j >> 1][(j & 1) * 2 + 1]);
                    #pragma unroll
                    for (int jj = 0; jj < 2; jj++)
                        LDSM_X4(B[jj][0], B[jj][1], B[jj][2], B[jj][3],
                                aWL + jj * (16 * STR2B) + chb + kb);
                    #pragma unroll
                    for (int i = 0; i < 2; i++)
                        #pragma unroll
                        for (int j = 0; j < 4; j++)
                            mma_bf16(acc[i][j][0], acc[i][j][1], acc[i][j][2], acc[i][j][3],
                                     Ah[i][0], Ah[i][1], Ah[i][2], Ah[i][3],
                                     B[j >> 1][(j & 1) * 2], B[j >> 1][(j & 1) * 2 + 1]);
                }
            }
            __syncthreads();                 // chunk consumed
            if (ch == 0)
                g2_issue_ch(sb, tid, row0, 1);
            else
                g2_issue_ch(sb, tid, (tile + gridDim.x) << 7, 0);
        }

        // epilogue: BN (+relu), fp32 store
        #pragma unroll
        for (int i = 0; i < 2; i++) {
            #pragma unroll
            for (int hf = 0; hf < 2; hf++) {
                int r = row0 + m0 + i * 16 + (lane >> 2) + hf * 8;
                if (r < N_NODES) {
                    float* dst = out + (size_t)r * 128;
                    #pragma unroll
                    for (int j = 0; j < 4; j++) {
                        int c = nb + j * 8 + 2 * q;
                        float z0 = fmaf(acc[i][j][hf * 2],     sAl[c],     sBe[c]);
                        float z1 = fmaf(acc[i][j][hf * 2 + 1], sAl[c + 1], sBe[c + 1]);
                        if (relu) { z0 = fmaxf(z0, 0.f); z1 = fmaxf(z1, 0.f); }
                        *(float2*)(dst + c) = make_float2(z0, z1);
                    }
                }
            }
        }
        __syncthreads();
    }
}

// ---------------- launch ----------------------------------------------------------
extern "C" void kernel_launch(void* const* d_in, const int* in_sizes, int n_in,
                              void* d_out, int out_size) {
    const float* x     = (const float*)d_in[0];
    const int*   ei    = (const int*)d_in[1];
    const float* W1    = (const float*)d_in[2];
    const float* b1    = (const float*)d_in[3];
    const float* bn1_g = (const float*)d_in[4];
    const float* bn1_b = (const float*)d_in[5];
    const float* bn1_m = (const float*)d_in[6];
    const float* bn1_v = (const float*)d_in[7];
    const float* W2    = (const float*)d_in[8];
    const float* b2    = (const float*)d_in[9];
    const float* bno_g = (const float*)d_in[10];
    const float* bno_b = (const float*)d_in[11];
    const float* bno_m = (const float*)d_in[12];
    const float* bno_v = (const float*)d_in[13];
    float* out = (float*)d_out;

    cudaFuncSetAttribute(k_gemm1, cudaFuncAttributeMaxDynamicSharedMemorySize, SMEM1);
    cudaFuncSetAttribute(k_gemm2, cudaFuncAttributeMaxDynamicSharedMemorySize, SMEM2);

    const int* src = ei;
    const int* dst = ei + EDGES;

    // launches 0..4: prep + CSR;  launch 5 = k_gemm1(L0)  (ncu -s 5 -c 1 target)
    k_prep<<<1280, 256>>>(W1, W2);
    k_hist<<<(EDGES + 255) / 256, 256>>>(dst);
    k_scan_a<<<NSCAN, 1024>>>();
    k_scan_c<<<NSCAN, 1024>>>();
    k_fill<<<(EDGES + 255) / 256, 256>>>(src, dst);

    const float* h = x;
    for (int l = 0; l < LAYERS; l++) {
        k_gemm1<<<GRID_G, 512, SMEM1>>>(l, h, b1 + (size_t)l * 256,
                bn1_g + (size_t)l * 256, bn1_b + (size_t)l * 256,
                bn1_m + (size_t)l * 256, bn1_v + (size_t)l * 256);
        k_gemm2<<<GRID_G, 512, SMEM2>>>(l, b2 + (size_t)l * 128,
                bno_g + (size_t)l * 128, bno_b + (size_t)l * 128,
                bno_m + (size_t)l * 128, bno_v + (size_t)l * 128,
                out, (l != LAYERS - 1) ? 1 : 0);
        h = out;
    }
}

// round 9
// speedup vs baseline: 2.2910x; 1.3416x over previous
#include <cuda_runtime.h>
#include <cuda_bf16.h>
#include <cstdint>

#define N_NODES 100000
#define EDGES   640000
#define LAYERS  5
#define BN_EPS  1e-5f
#define NT      1563         // ceil(100000/64): M-tile 64 for both GEMMs
#define GRID_G  148
#define NSCAN   98

// ---------------- static scratch ------------------------------------------------
__device__ __nv_bfloat16 g_a_hi[(size_t)N_NODES * 128];
__device__ __nv_bfloat16 g_a_lo[(size_t)N_NODES * 128];
__device__ __nv_bfloat16 g_z_hi[(size_t)N_NODES * 256];
__device__ __nv_bfloat16 g_z_lo[(size_t)N_NODES * 256];
__device__ __nv_bfloat16 g_w1t[LAYERS * 2 * 32768];   // [l][term][n=256][k=128]
__device__ __nv_bfloat16 g_w2t[LAYERS * 2 * 32768];   // [l][term][n=128][k=256]
__device__ int g_rowptr[N_NODES + 1];
__device__ int g_cnt[N_NODES];
__device__ int g_cursor[N_NODES];
__device__ int g_srcs[EDGES];
__device__ int g_part[NSCAN];

// ---------------- helpers -------------------------------------------------------
__device__ __forceinline__ uint32_t smem_u32(const void* p) {
    uint32_t a;
    asm("{ .reg .u64 t; cvta.to.shared.u64 t, %1; cvt.u32.u64 %0, t; }" : "=r"(a) : "l"(p));
    return a;
}
__device__ __forceinline__ uint32_t pack_bf(__nv_bfloat16 a, __nv_bfloat16 b) {
    return ((uint32_t)__bfloat16_as_ushort(b) << 16) | (uint32_t)__bfloat16_as_ushort(a);
}
__device__ __forceinline__ void split_bf(float x, __nv_bfloat16& h, __nv_bfloat16& l) {
    h = __float2bfloat16(x);
    l = __float2bfloat16(x - __bfloat162float(h));
}

#define LDSM_X4(r0, r1, r2, r3, addr) \
    asm volatile("ldmatrix.sync.aligned.m8n8.x4.shared.b16 {%0,%1,%2,%3}, [%4];" \
        : "=r"(r0), "=r"(r1), "=r"(r2), "=r"(r3) : "r"(addr))

__device__ __forceinline__ void mma_bf16(float& c0, float& c1, float& c2, float& c3,
        uint32_t a0, uint32_t a1, uint32_t a2, uint32_t a3, uint32_t b0, uint32_t b1) {
    asm volatile("mma.sync.aligned.m16n8k16.row.col.f32.bf16.bf16.f32 "
        "{%0,%1,%2,%3}, {%4,%5,%6,%7}, {%8,%9}, {%0,%1,%2,%3};"
        : "+f"(c0), "+f"(c1), "+f"(c2), "+f"(c3)
        : "r"(a0), "r"(a1), "r"(a2), "r"(a3), "r"(b0), "r"(b1));
}

__device__ __forceinline__ void cp16(uint32_t dst, const void* src, uint32_t srcsz) {
    asm volatile("cp.async.ca.shared.global [%0], [%1], 16, %2;"
                 :: "r"(dst), "l"(src), "r"(srcsz) : "memory");
}
#define CP_COMMIT() asm volatile("cp.async.commit_group;" ::: "memory")
__device__ __forceinline__ void cp_wait_dyn(int n) {
    switch (n) {
        case 0: asm volatile("cp.async.wait_group 0;" ::: "memory"); break;
        case 1: asm volatile("cp.async.wait_group 1;" ::: "memory"); break;
        case 2: asm volatile("cp.async.wait_group 2;" ::: "memory"); break;
        case 3: asm volatile("cp.async.wait_group 3;" ::: "memory"); break;
        default: asm volatile("cp.async.wait_group 0;" ::: "memory"); break;
    }
}

// ---------------- prep: W split-bf16 transpose + CSR zero (fused) ----------------
__global__ void k_prep(const float* __restrict__ W1, const float* __restrict__ W2) {
    int i = blockIdx.x * blockDim.x + threadIdx.x;
    const int TOT = LAYERS * 32768;
    if (i < N_NODES) { g_cnt[i] = 0; g_cursor[i] = 0; }
    if (i < TOT) {
        int l = i >> 15, r = i & 32767;
        int k = r >> 8, n = r & 255;           // W1[l][k][n]
        __nv_bfloat16 hi, lo;
        split_bf(W1[i], hi, lo);
        g_w1t[(size_t)l * 65536 + n * 128 + k] = hi;
        g_w1t[(size_t)l * 65536 + 32768 + n * 128 + k] = lo;
    } else if (i < 2 * TOT) {
        int j = i - TOT;
        int l = j >> 15, r = j & 32767;
        int k = r >> 7, n = r & 127;           // W2[l][k][n]
        __nv_bfloat16 hi, lo;
        split_bf(W2[j], hi, lo);
        g_w2t[(size_t)l * 65536 + n * 256 + k] = hi;
        g_w2t[(size_t)l * 65536 + 32768 + n * 256 + k] = lo;
    }
}

// ---------------- CSR build ------------------------------------------------------
__global__ void k_hist(const int* __restrict__ dst) {
    int e = blockIdx.x * blockDim.x + threadIdx.x;
    if (e < EDGES) atomicAdd(&g_cnt[dst[e]], 1);
}
__global__ void k_scan_a() {
    __shared__ int s[1024];
    int t = threadIdx.x, b = blockIdx.x;
    int i = b * 1024 + t;
    int v = (i < N_NODES) ? g_cnt[i] : 0;
    s[t] = v;
    __syncthreads();
    #pragma unroll
    for (int off = 1; off < 1024; off <<= 1) {
        int u = (t >= off) ? s[t - off] : 0;
        __syncthreads();
        s[t] += u;
        __syncthreads();
    }
    if (i < N_NODES) g_rowptr[i + 1] = s[t];
    if (t == 1023) g_part[b] = s[t];
}
__global__ void k_scan_c() {
    __shared__ int pre;
    int t = threadIdx.x, b = blockIdx.x;
    if (t == 0) {
        int acc = 0;
        for (int j = 0; j < b; j++) acc += g_part[j];
        pre = acc;
    }
    __syncthreads();
    int i = b * 1024 + t;
    if (i < N_NODES) g_rowptr[i + 1] += pre;
    if (i == 0) g_rowptr[0] = 0;
}
__global__ void k_fill(const int* __restrict__ src, const int* __restrict__ dst) {
    int e = blockIdx.x * blockDim.x + threadIdx.x;
    if (e < EDGES) {
        int d = dst[e];
        int p = g_rowptr[d] + atomicAdd(&g_cursor[d], 1);
        g_srcs[p] = src[e];
    }
}

// ---------------- aggregation: agg = h_i + sum h_j -> split bf16 -----------------
__global__ void k_aggregate(const float* __restrict__ h) {
    int gw = (blockIdx.x * blockDim.x + threadIdx.x) >> 5;
    int lane = threadIdx.x & 31;
    if (gw >= N_NODES) return;
    const float4* hv = (const float4*)h;
    float4 acc = __ldg(&hv[(size_t)gw * 32 + lane]);
    int e0 = g_rowptr[gw], e1 = g_rowptr[gw + 1];
    for (int e = e0; e < e1; e++) {
        int j = g_srcs[e];
        float4 v = __ldg(&hv[(size_t)j * 32 + lane]);
        acc.x += v.x; acc.y += v.y; acc.z += v.z; acc.w += v.w;
    }
    __nv_bfloat16 h0, h1, h2, h3, l0, l1, l2, l3;
    split_bf(acc.x, h0, l0); split_bf(acc.y, h1, l1);
    split_bf(acc.z, h2, l2); split_bf(acc.w, h3, l3);
    uint2 ph, pl;
    ph.x = pack_bf(h0, h1); ph.y = pack_bf(h2, h3);
    pl.x = pack_bf(l0, l1); pl.y = pack_bf(l2, l3);
    ((uint2*)g_a_hi)[(size_t)gw * 32 + lane] = ph;
    ((uint2*)g_a_lo)[(size_t)gw * 32 + lane] = pl;
}

// ---------------- SMEM layouts ----------------------------------------------------
// GEMM1: alpha|beta | W hi/lo [256][272] | A hi/lo [64][272]
#define STR1B    272
#define G1_ALPHA 0
#define G1_BETA  1024
#define G1_W     2048
#define G1_WLOFF 69632
#define G1_A     141312
#define G1_LO    17408
#define SMEM1    176128
// GEMM2: W hi/lo [128][528] | A(chunk) hi/lo [64][272] | alpha|beta
#define STR2B    528
#define G2_W     0
#define G2_WL    67584
#define G2_Z     135168
#define G2_ZLO   17408
#define G2_ALPHA 169984
#define G2_BETA  170496
#define SMEM2    171008

// ---- cp.async tile issuers: 4 groups per tile, group g == ksteps {2g, 2g+1} -----
__device__ __forceinline__ void g1_issue(uint32_t sb, int tid, int row0) {
    int hl = tid >> 8;
    int t = tid & 255;
    int r = t >> 2, c = t & 3;
    int gr = row0 + r;
    uint32_t p = (gr < N_NODES) ? 16u : 0u;
    const char* gsrc = (const char*)(hl ? g_a_lo : g_a_hi) + (size_t)gr * 256 + c * 16;
    uint32_t dsm = sb + G1_A + hl * G1_LO + r * STR1B + c * 16;
    #pragma unroll
    for (int g = 0; g < 4; g++) {
        cp16(dsm + g * 64, gsrc + g * 64, p);
        CP_COMMIT();
    }
}
__device__ __forceinline__ void g2_issue(uint32_t sb, int tid, int row0, int ch) {
    int hl = tid >> 8;
    int t = tid & 255;
    int r = t >> 2, c = t & 3;
    int gr = row0 + r;
    uint32_t p = (gr < N_NODES) ? 16u : 0u;
    const char* gsrc = (const char*)(hl ? g_z_lo : g_z_hi) + (size_t)gr * 512 + ch * 256 + c * 16;
    uint32_t dsm = sb + G2_Z + hl * G2_ZLO + r * STR1B + c * 16;
    #pragma unroll
    for (int g = 0; g < 4; g++) {
        cp16(dsm + g * 64, gsrc + g * 64, p);
        CP_COMMIT();
    }
}

// ---------------- GEMM1: z = relu(BN1(agg @ W1 + b1)),  [N,128]x[128,256] --------
// 512 thr, 16 warps: 2m x 8n grid, warp tile m32 x n32; M-tile 64
__global__ void __launch_bounds__(512, 1) k_gemm1(
    int layer, const float* __restrict__ bias,
    const float* __restrict__ bn_g, const float* __restrict__ bn_b,
    const float* __restrict__ bn_m, const float* __restrict__ bn_v)
{
    extern __shared__ char sm[];
    uint32_t sb = smem_u32(sm);
    int tid = threadIdx.x, lane = tid & 31, wid = tid >> 5;

    g1_issue(sb, tid, blockIdx.x << 6);   // prefetch first A tile

    {   // W hi+lo into padded smem [n=256][k=128]
        const uint4* s = (const uint4*)(g_w1t + (size_t)layer * 65536);
        #pragma unroll 2
        for (int i = tid; i < 4096; i += 512) {
            int r = i >> 4, c = i & 15;
            *(uint4*)(sm + G1_W + r * STR1B + c * 16) = s[i];
            *(uint4*)(sm + G1_W + G1_WLOFF + r * STR1B + c * 16) = s[i + 4096];
        }
    }
    float* sAl = (float*)(sm + G1_ALPHA);
    float* sBe = (float*)(sm + G1_BETA);
    if (tid < 256) {
        float s = bn_g[tid] * rsqrtf(bn_v[tid] + BN_EPS);
        sAl[tid] = s;
        sBe[tid] = (bias[tid] - bn_m[tid]) * s + bn_b[tid];
    }
    __syncthreads();

    int m0 = (wid >> 3) * 32, n0 = (wid & 7) * 32;
    uint32_t aoffA = (uint32_t)((m0 + (lane & 15)) * STR1B + ((lane >> 4) << 4));
    uint32_t aAH = sb + G1_A + aoffA;
    uint32_t aAL = aAH + G1_LO;
    uint32_t boff = (uint32_t)((n0 + ((lane >> 4) << 3) + (lane & 7)) * STR1B + (((lane >> 3) & 1) << 4));
    uint32_t aWH = sb + G1_W + boff;
    uint32_t aWL = sb + G1_W + G1_WLOFF + boff;
    int q = lane & 3;

    for (int tile = blockIdx.x; tile < NT; tile += gridDim.x) {
        int row0 = tile << 6;

        float acc[2][4][4];
        #pragma unroll
        for (int i = 0; i < 2; i++)
            #pragma unroll
            for (int j = 0; j < 4; j++)
                #pragma unroll
                for (int f = 0; f < 4; f++) acc[i][j][f] = 0.f;

        #pragma unroll
        for (int kp = 0; kp < 4; kp++) {
            cp_wait_dyn(3 - kp);
            __syncthreads();
            #pragma unroll
            for (int kq = 0; kq < 2; kq++) {
                uint32_t kb = (uint32_t)(kp * 2 + kq) << 5;
                uint32_t Ah[2][4], Alr[2][4], B[4];
                #pragma unroll
                for (int i = 0; i < 2; i++) {
                    LDSM_X4(Ah[i][0], Ah[i][1], Ah[i][2], Ah[i][3], aAH + i * (16 * STR1B) + kb);
                    LDSM_X4(Alr[i][0], Alr[i][1], Alr[i][2], Alr[i][3], aAL + i * (16 * STR1B) + kb);
                }
                #pragma unroll
                for (int j2 = 0; j2 < 2; j2++) {
                    LDSM_X4(B[0], B[1], B[2], B[3], aWH + j2 * (16 * STR1B) + kb);
                    #pragma unroll
                    for (int i = 0; i < 2; i++)
                        #pragma unroll
                        for (int jj = 0; jj < 2; jj++)
                            mma_bf16(acc[i][j2*2+jj][0], acc[i][j2*2+jj][1],
                                     acc[i][j2*2+jj][2], acc[i][j2*2+jj][3],
                                     Ah[i][0], Ah[i][1], Ah[i][2], Ah[i][3],
                                     B[jj*2], B[jj*2+1]);
                    #pragma unroll
                    for (int i = 0; i < 2; i++)
                        #pragma unroll
                        for (int jj = 0; jj < 2; jj++)
                            mma_bf16(acc[i][j2*2+jj][0], acc[i][j2*2+jj][1],
                                     acc[i][j2*2+jj][2], acc[i][j2*2+jj][3],
                                     Alr[i][0], Alr[i][1], Alr[i][2], Alr[i][3],
                                     B[jj*2], B[jj*2+1]);
                    LDSM_X4(B[0], B[1], B[2], B[3], aWL + j2 * (16 * STR1B) + kb);
                    #pragma unroll
                    for (int i = 0; i < 2; i++)
                        #pragma unroll
                        for (int jj = 0; jj < 2; jj++)
                            mma_bf16(acc[i][j2*2+jj][0], acc[i][j2*2+jj][1],
                                     acc[i][j2*2+jj][2], acc[i][j2*2+jj][3],
                                     Ah[i][0], Ah[i][1], Ah[i][2], Ah[i][3],
                                     B[jj*2], B[jj*2+1]);
                }
            }
        }
        __syncthreads();                    // all warps done reading A smem
        g1_issue(sb, tid, (tile + gridDim.x) << 6);   // prefetch next tile

        // epilogue: BN + relu + split-bf16 store of z (overlaps prefetch)
        uint32_t* zh = (uint32_t*)g_z_hi;
        uint32_t* zl = (uint32_t*)g_z_lo;
        #pragma unroll
        for (int i = 0; i < 2; i++) {
            #pragma unroll
            for (int hf = 0; hf < 2; hf++) {
                int r = row0 + m0 + i * 16 + (lane >> 2) + hf * 8;
                if (r < N_NODES) {
                    size_t rb = (size_t)r * 128 + (n0 >> 1) + q;
                    #pragma unroll
                    for (int j = 0; j < 4; j++) {
                        int c = n0 + j * 8 + 2 * q;
                        float z0 = fmaxf(fmaf(acc[i][j][hf * 2],     sAl[c],     sBe[c]),     0.f);
                        float z1 = fmaxf(fmaf(acc[i][j][hf * 2 + 1], sAl[c + 1], sBe[c + 1]), 0.f);
                        __nv_bfloat16 h0, h1, l0, l1;
                        split_bf(z0, h0, l0); split_bf(z1, h1, l1);
                        zh[rb + j * 4] = pack_bf(h0, h1);
                        zl[rb + j * 4] = pack_bf(l0, l1);
                    }
                }
            }
        }
    }
}

// ---------------- GEMM2: h = BN_o(z @ W2 + b2)(+relu),  [N,256]x[256,128] --------
// 512 thr, 16 warps: 2m x 8n grid, warp tile m32 x n16; M-tile 64; K in 2 chunks
__global__ void __launch_bounds__(512, 1) k_gemm2(
    int layer, const float* __restrict__ bias,
    const float* __restrict__ bn_g, const float* __restrict__ bn_b,
    const float* __restrict__ bn_m, const float* __restrict__ bn_v,
    float* __restrict__ out, int relu)
{
    extern __shared__ char sm[];
    uint32_t sb = smem_u32(sm);
    int tid = threadIdx.x, lane = tid & 31, wid = tid >> 5;

    g2_issue(sb, tid, blockIdx.x << 6, 0);

    {
        const uint4* s = (const uint4*)(g_w2t + (size_t)layer * 65536);
        #pragma unroll 2
        for (int i = tid; i < 4096; i += 512) {
            int r = i >> 5, c = i & 31;
            *(uint4*)(sm + G2_W + r * STR2B + c * 16) = s[i];
            *(uint4*)(sm + G2_WL + r * STR2B + c * 16) = s[i + 4096];
        }
    }
    float* sAl = (float*)(sm + G2_ALPHA);
    float* sBe = (float*)(sm + G2_BETA);
    if (tid < 128) {
        float s = bn_g[tid] * rsqrtf(bn_v[tid] + BN_EPS);
        sAl[tid] = s;
        sBe[tid] = (bias[tid] - bn_m[tid]) * s + bn_b[tid];
    }
    __syncthreads();

    int m0 = (wid >> 3) * 32, n0 = (wid & 7) * 16;
    uint32_t aoff = (uint32_t)((m0 + (lane & 15)) * STR1B + ((lane >> 4) << 4));
    uint32_t aZH = sb + G2_Z + aoff;
    uint32_t aZL = aZH + G2_ZLO;
    uint32_t boff = (uint32_t)((n0 + ((lane >> 4) << 3) + (lane & 7)) * STR2B + (((lane >> 3) & 1) << 4));
    uint32_t aWH = sb + G2_W + boff;
    uint32_t aWL = sb + G2_WL + boff;
    int q = lane & 3;

    for (int tile = blockIdx.x; tile < NT; tile += gridDim.x) {
        int row0 = tile << 6;

        float acc[2][2][4];
        #pragma unroll
        for (int i = 0; i < 2; i++)
            #pragma unroll
            for (int j = 0; j < 2; j++)
                #pragma unroll
                for (int f = 0; f < 4; f++) acc[i][j][f] = 0.f;

        #pragma unroll 1
        for (int ch = 0; ch < 2; ch++) {
            uint32_t chb = (uint32_t)ch * 256;
            #pragma unroll
            for (int kp = 0; kp < 4; kp++) {
                cp_wait_dyn(3 - kp);
                __syncthreads();
                #pragma unroll
                for (int kq = 0; kq < 2; kq++) {
                    uint32_t kb = (uint32_t)(kp * 2 + kq) << 5;
                    uint32_t Ah[2][4], Alr[2][4], B[4];
                    #pragma unroll
                    for (int i = 0; i < 2; i++) {
                        LDSM_X4(Ah[i][0], Ah[i][1], Ah[i][2], Ah[i][3], aZH + i * (16 * STR1B) + kb);
                        LDSM_X4(Alr[i][0], Alr[i][1], Alr[i][2], Alr[i][3], aZL + i * (16 * STR1B) + kb);
                    }
                    LDSM_X4(B[0], B[1], B[2], B[3], aWH + chb + kb);
                    #pragma unroll
                    for (int i = 0; i < 2; i++)
                        #pragma unroll
                        for (int j = 0; j < 2; j++)
                            mma_bf16(acc[i][j][0], acc[i][j][1], acc[i][j][2], acc[i][j][3],
                                     Ah[i][0], Ah[i][1], Ah[i][2], Ah[i][3],
                                     B[j*2], B[j*2+1]);
                    #pragma unroll
                    for (int i = 0; i < 2; i++)
                        #pragma unroll
                        for (int j = 0; j < 2; j++)
                            mma_bf16(acc[i][j][0], acc[i][j][1], acc[i][j][2], acc[i][j][3],
                                     Alr[i][0], Alr[i][1], Alr[i][2], Alr[i][3],
                                     B[j*2], B[j*2+1]);
                    LDSM_X4(B[0], B[1], B[2], B[3], aWL + chb + kb);
                    #pragma unroll
                    for (int i = 0; i < 2; i++)
                        #pragma unroll
                        for (int j = 0; j < 2; j++)
                            mma_bf16(acc[i][j][0], acc[i][j][1], acc[i][j][2], acc[i][j][3],
                                     Ah[i][0], Ah[i][1], Ah[i][2], Ah[i][3],
                                     B[j*2], B[j*2+1]);
                }
            }
            __syncthreads();                 // chunk consumed
            if (ch == 0)
                g2_issue(sb, tid, row0, 1);
            else
                g2_issue(sb, tid, (tile + gridDim.x) << 6, 0);
        }

        // epilogue: BN (+relu), fp32 store
        #pragma unroll
        for (int i = 0; i < 2; i++) {
            #pragma unroll
            for (int hf = 0; hf < 2; hf++) {
                int r = row0 + m0 + i * 16 + (lane >> 2) + hf * 8;
                if (r < N_NODES) {
                    float* dst = out + (size_t)r * 128;
                    #pragma unroll
                    for (int j = 0; j < 2; j++) {
                        int c = n0 + j * 8 + 2 * q;
                        float z0 = fmaf(acc[i][j][hf * 2],     sAl[c],     sBe[c]);
                        float z1 = fmaf(acc[i][j][hf * 2 + 1], sAl[c + 1], sBe[c + 1]);
                        if (relu) { z0 = fmaxf(z0, 0.f); z1 = fmaxf(z1, 0.f); }
                        *(float2*)(dst + c) = make_float2(z0, z1);
                    }
                }
            }
        }
    }
}

// ---------------- launch ----------------------------------------------------------
extern "C" void kernel_launch(void* const* d_in, const int* in_sizes, int n_in,
                              void* d_out, int out_size) {
    const float* x     = (const float*)d_in[0];
    const int*   ei    = (const int*)d_in[1];
    const float* W1    = (const float*)d_in[2];
    const float* b1    = (const float*)d_in[3];
    const float* bn1_g = (const float*)d_in[4];
    const float* bn1_b = (const float*)d_in[5];
    const float* bn1_m = (const float*)d_in[6];
    const float* bn1_v = (const float*)d_in[7];
    const float* W2    = (const float*)d_in[8];
    const float* b2    = (const float*)d_in[9];
    const float* bno_g = (const float*)d_in[10];
    const float* bno_b = (const float*)d_in[11];
    const float* bno_m = (const float*)d_in[12];
    const float* bno_v = (const float*)d_in[13];
    float* out = (float*)d_out;

    cudaFuncSetAttribute(k_gemm1, cudaFuncAttributeMaxDynamicSharedMemorySize, SMEM1);
    cudaFuncSetAttribute(k_gemm2, cudaFuncAttributeMaxDynamicSharedMemorySize, SMEM2);

    const int* src = ei;
    const int* dst = ei + EDGES;

    k_prep<<<1280, 256>>>(W1, W2);
    k_hist<<<(EDGES + 255) / 256, 256>>>(dst);
    k_scan_a<<<NSCAN, 1024>>>();
    k_scan_c<<<NSCAN, 1024>>>();
    k_fill<<<(EDGES + 255) / 256, 256>>>(src, dst);

    const float* h = x;
    for (int l = 0; l < LAYERS; l++) {
        k_aggregate<<<(N_NODES * 32 + 255) / 256, 256>>>(h);
        k_gemm1<<<GRID_G, 512, SMEM1>>>(l, b1 + (size_t)l * 256,
                bn1_g + (size_t)l * 256, bn1_b + (size_t)l * 256,
                bn1_m + (size_t)l * 256, bn1_v + (size_t)l * 256);
        k_gemm2<<<GRID_G, 512, SMEM2>>>(l, b2 + (size_t)l * 128,
                bno_g + (size_t)l * 128, bno_b + (size_t)l * 128,
                bno_m + (size_t)l * 128, bno_v + (size_t)l * 128,
                out, (l != LAYERS - 1) ? 1 : 0);
        h = out;
    }
}

// round 10
// speedup vs baseline: 2.3305x; 1.0173x over previous
#include <cuda_runtime.h>
#include <cuda_bf16.h>
#include <cstdint>

#define N_NODES 100000
#define EDGES   640000
#define LAYERS  5
#define BN_EPS  1e-5f
#define NT      1563         // ceil(100000/64): M-tile 64 for both GEMMs
#define GRID_G  148
#define NSCAN   98

// ---------------- static scratch ------------------------------------------------
__device__ __nv_bfloat16 g_a_hi[(size_t)N_NODES * 128];
__device__ __nv_bfloat16 g_a_lo[(size_t)N_NODES * 128];
__device__ __nv_bfloat16 g_z_hi[(size_t)N_NODES * 256];
__device__ __nv_bfloat16 g_z_lo[(size_t)N_NODES * 256];
__device__ __nv_bfloat16 g_w1t[LAYERS * 2 * 32768];   // [l][term][n=256][k=128]
__device__ __nv_bfloat16 g_w2t[LAYERS * 2 * 32768];   // [l][term][n=128][k=256]
__device__ int g_rowptr[N_NODES + 1];
__device__ int g_cnt[N_NODES];
__device__ int g_cursor[N_NODES];
__device__ int g_srcs[EDGES];
__device__ int g_part[NSCAN];

// ---------------- helpers -------------------------------------------------------
__device__ __forceinline__ uint32_t smem_u32(const void* p) {
    uint32_t a;
    asm("{ .reg .u64 t; cvta.to.shared.u64 t, %1; cvt.u32.u64 %0, t; }" : "=r"(a) : "l"(p));
    return a;
}
__device__ __forceinline__ uint32_t pack_bf(__nv_bfloat16 a, __nv_bfloat16 b) {
    return ((uint32_t)__bfloat16_as_ushort(b) << 16) | (uint32_t)__bfloat16_as_ushort(a);
}
__device__ __forceinline__ void split_bf(float x, __nv_bfloat16& h, __nv_bfloat16& l) {
    h = __float2bfloat16(x);
    l = __float2bfloat16(x - __bfloat162float(h));
}

#define LDSM_X4(r0, r1, r2, r3, addr) \
    asm volatile("ldmatrix.sync.aligned.m8n8.x4.shared.b16 {%0,%1,%2,%3}, [%4];" \
        : "=r"(r0), "=r"(r1), "=r"(r2), "=r"(r3) : "r"(addr))

__device__ __forceinline__ void mma_bf16(float& c0, float& c1, float& c2, float& c3,
        uint32_t a0, uint32_t a1, uint32_t a2, uint32_t a3, uint32_t b0, uint32_t b1) {
    asm volatile("mma.sync.aligned.m16n8k16.row.col.f32.bf16.bf16.f32 "
        "{%0,%1,%2,%3}, {%4,%5,%6,%7}, {%8,%9}, {%0,%1,%2,%3};"
        : "+f"(c0), "+f"(c1), "+f"(c2), "+f"(c3)
        : "r"(a0), "r"(a1), "r"(a2), "r"(a3), "r"(b0), "r"(b1));
}

__device__ __forceinline__ void cp16(uint32_t dst, const void* src, uint32_t srcsz) {
    asm volatile("cp.async.ca.shared.global [%0], [%1], 16, %2;"
                 :: "r"(dst), "l"(src), "r"(srcsz) : "memory");
}
#define CP_COMMIT() asm volatile("cp.async.commit_group;" ::: "memory")
#define CP_WAIT0()  asm volatile("cp.async.wait_group 0;" ::: "memory")

// ---------------- prep: W split-bf16 transpose + CSR zero (fused) ----------------
__global__ void k_prep(const float* __restrict__ W1, const float* __restrict__ W2) {
    int i = blockIdx.x * blockDim.x + threadIdx.x;
    const int TOT = LAYERS * 32768;
    if (i < N_NODES) { g_cnt[i] = 0; g_cursor[i] = 0; }
    if (i < TOT) {
        int l = i >> 15, r = i & 32767;
        int k = r >> 8, n = r & 255;           // W1[l][k][n]
        __nv_bfloat16 hi, lo;
        split_bf(W1[i], hi, lo);
        g_w1t[(size_t)l * 65536 + n * 128 + k] = hi;
        g_w1t[(size_t)l * 65536 + 32768 + n * 128 + k] = lo;
    } else if (i < 2 * TOT) {
        int j = i - TOT;
        int l = j >> 15, r = j & 32767;
        int k = r >> 7, n = r & 127;           // W2[l][k][n]
        __nv_bfloat16 hi, lo;
        split_bf(W2[j], hi, lo);
        g_w2t[(size_t)l * 65536 + n * 256 + k] = hi;
        g_w2t[(size_t)l * 65536 + 32768 + n * 256 + k] = lo;
    }
}

// ---------------- CSR build ------------------------------------------------------
__global__ void k_hist(const int* __restrict__ dst) {
    int e = blockIdx.x * blockDim.x + threadIdx.x;
    if (e < EDGES) atomicAdd(&g_cnt[dst[e]], 1);
}
__global__ void k_scan_a() {
    __shared__ int s[1024];
    int t = threadIdx.x, b = blockIdx.x;
    int i = b * 1024 + t;
    int v = (i < N_NODES) ? g_cnt[i] : 0;
    s[t] = v;
    __syncthreads();
    #pragma unroll
    for (int off = 1; off < 1024; off <<= 1) {
        int u = (t >= off) ? s[t - off] : 0;
        __syncthreads();
        s[t] += u;
        __syncthreads();
    }
    if (i < N_NODES) g_rowptr[i + 1] = s[t];
    if (t == 1023) g_part[b] = s[t];
}
__global__ void k_scan_c() {
    __shared__ int pre;
    int t = threadIdx.x, b = blockIdx.x;
    if (t == 0) {
        int acc = 0;
        for (int j = 0; j < b; j++) acc += g_part[j];
        pre = acc;
    }
    __syncthreads();
    int i = b * 1024 + t;
    if (i < N_NODES) g_rowptr[i + 1] += pre;
    if (i == 0) g_rowptr[0] = 0;
}
__global__ void k_fill(const int* __restrict__ src, const int* __restrict__ dst) {
    int e = blockIdx.x * blockDim.x + threadIdx.x;
    if (e < EDGES) {
        int d = dst[e];
        int p = g_rowptr[d] + atomicAdd(&g_cursor[d], 1);
        g_srcs[p] = src[e];
    }
}

// ---------------- aggregation: agg = h_i + sum h_j -> split bf16 -----------------
__global__ void k_aggregate(const float* __restrict__ h) {
    int gw = (blockIdx.x * blockDim.x + threadIdx.x) >> 5;
    int lane = threadIdx.x & 31;
    if (gw >= N_NODES) return;
    const float4* hv = (const float4*)h;
    float4 acc = __ldg(&hv[(size_t)gw * 32 + lane]);
    int e0 = g_rowptr[gw], e1 = g_rowptr[gw + 1];
    for (int e = e0; e < e1; e++) {
        int j = g_srcs[e];
        float4 v = __ldg(&hv[(size_t)j * 32 + lane]);
        acc.x += v.x; acc.y += v.y; acc.z += v.z; acc.w += v.w;
    }
    __nv_bfloat16 h0, h1, h2, h3, l0, l1, l2, l3;
    split_bf(acc.x, h0, l0); split_bf(acc.y, h1, l1);
    split_bf(acc.z, h2, l2); split_bf(acc.w, h3, l3);
    uint2 ph, pl;
    ph.x = pack_bf(h0, h1); ph.y = pack_bf(h2, h3);
    pl.x = pack_bf(l0, l1); pl.y = pack_bf(l2, l3);
    ((uint2*)g_a_hi)[(size_t)gw * 32 + lane] = ph;
    ((uint2*)g_a_lo)[(size_t)gw * 32 + lane] = pl;
}

// ---------------- SMEM layouts ----------------------------------------------------
// GEMM1: alpha|beta | W hi/lo [256][272] | A double buf [2][hi/lo][64][272]
#define STR1B    272
#define G1_ALPHA 0
#define G1_BETA  1024
#define G1_W     2048
#define G1_WLOFF 69632
#define G1_A     141312
#define G1_BUF   34816
#define G1_LO    17408
#define SMEM1    210944
// GEMM2: W hi/lo [128][528] | chunk double buf [2][hi/lo][64][272] | alpha|beta
#define STR2B    528
#define G2_W     0
#define G2_WL    67584
#define G2_Z     135168
#define G2_BUF   34816
#define G2_LO    17408
#define G2_ALPHA 204800
#define G2_BETA  205312
#define SMEM2    205824

// ---- cp.async full-tile issuers: one commit group per issue ---------------------
__device__ __forceinline__ void g1_issue(uint32_t sb, int tid, int row0, int buf) {
    int hl = tid >> 8;
    int t = tid & 255;
    int r = t >> 2, c = t & 3;
    int gr = row0 + r;
    uint32_t p = (gr < N_NODES) ? 16u : 0u;
    const char* gsrc = (const char*)(hl ? g_a_lo : g_a_hi) + (size_t)gr * 256 + c * 16;
    uint32_t dsm = sb + G1_A + buf * G1_BUF + hl * G1_LO + r * STR1B + c * 16;
    #pragma unroll
    for (int g = 0; g < 4; g++) cp16(dsm + g * 64, gsrc + g * 64, p);
    CP_COMMIT();
}
__device__ __forceinline__ void g2_issue(uint32_t sb, int tid, int row0, int ch, int buf) {
    int hl = tid >> 8;
    int t = tid & 255;
    int r = t >> 2, c = t & 3;
    int gr = row0 + r;
    uint32_t p = (gr < N_NODES) ? 16u : 0u;
    const char* gsrc = (const char*)(hl ? g_z_lo : g_z_hi) + (size_t)gr * 512 + ch * 256 + c * 16;
    uint32_t dsm = sb + G2_Z + buf * G2_BUF + hl * G2_LO + r * STR1B + c * 16;
    #pragma unroll
    for (int g = 0; g < 4; g++) cp16(dsm + g * 64, gsrc + g * 64, p);
    CP_COMMIT();
}

// ---------------- GEMM1: z = relu(BN1(agg @ W1 + b1)),  [N,128]x[128,256] --------
// 512 thr, 16 warps: 2m x 8n, warp tile m32 x n32; M-tile 64; double-buffered A
__global__ void __launch_bounds__(512, 1) k_gemm1(
    int layer, const float* __restrict__ bias,
    const float* __restrict__ bn_g, const float* __restrict__ bn_b,
    const float* __restrict__ bn_m, const float* __restrict__ bn_v)
{
    extern __shared__ char sm[];
    uint32_t sb = smem_u32(sm);
    int tid = threadIdx.x, lane = tid & 31, wid = tid >> 5;

    g1_issue(sb, tid, blockIdx.x << 6, 0);   // prefetch first tile into buf0

    {   // W hi+lo into padded smem [n=256][k=128]
        const uint4* s = (const uint4*)(g_w1t + (size_t)layer * 65536);
        #pragma unroll 2
        for (int i = tid; i < 4096; i += 512) {
            int r = i >> 4, c = i & 15;
            *(uint4*)(sm + G1_W + r * STR1B + c * 16) = s[i];
            *(uint4*)(sm + G1_W + G1_WLOFF + r * STR1B + c * 16) = s[i + 4096];
        }
    }
    float* sAl = (float*)(sm + G1_ALPHA);
    float* sBe = (float*)(sm + G1_BETA);
    if (tid < 256) {
        float s = bn_g[tid] * rsqrtf(bn_v[tid] + BN_EPS);
        sAl[tid] = s;
        sBe[tid] = (bias[tid] - bn_m[tid]) * s + bn_b[tid];
    }
    __syncthreads();

    int m0 = (wid >> 3) * 32, n0 = (wid & 7) * 32;
    uint32_t aoffA = (uint32_t)((m0 + (lane & 15)) * STR1B + ((lane >> 4) << 4));
    uint32_t boff = (uint32_t)((n0 + ((lane >> 4) << 3) + (lane & 7)) * STR1B + (((lane >> 3) & 1) << 4));
    uint32_t aWH = sb + G1_W + boff;
    uint32_t aWL = sb + G1_W + G1_WLOFF + boff;
    int q = lane & 3;

    int buf = 0;
    for (int tile = blockIdx.x; tile < NT; tile += gridDim.x) {
        int row0 = tile << 6;
        CP_WAIT0();            // current buffer ready
        __syncthreads();       // all warps past previous tile's reads
        g1_issue(sb, tid, (tile + gridDim.x) << 6, buf ^ 1);   // prefetch next

        uint32_t aAH = sb + G1_A + buf * G1_BUF + aoffA;
        uint32_t aAL = aAH + G1_LO;

        float acc[2][4][4];
        #pragma unroll
        for (int i = 0; i < 2; i++)
            #pragma unroll
            for (int j = 0; j < 4; j++)
                #pragma unroll
                for (int f = 0; f < 4; f++) acc[i][j][f] = 0.f;

        #pragma unroll 2
        for (int ks = 0; ks < 8; ks++) {
            uint32_t kb = (uint32_t)ks << 5;
            uint32_t Ah[2][4], Alr[2][4], B[4];
            #pragma unroll
            for (int i = 0; i < 2; i++) {
                LDSM_X4(Ah[i][0], Ah[i][1], Ah[i][2], Ah[i][3], aAH + i * (16 * STR1B) + kb);
                LDSM_X4(Alr[i][0], Alr[i][1], Alr[i][2], Alr[i][3], aAL + i * (16 * STR1B) + kb);
            }
            #pragma unroll
            for (int j2 = 0; j2 < 2; j2++) {
                LDSM_X4(B[0], B[1], B[2], B[3], aWH + j2 * (16 * STR1B) + kb);
                #pragma unroll
                for (int i = 0; i < 2; i++)
                    #pragma unroll
                    for (int jj = 0; jj < 2; jj++)
                        mma_bf16(acc[i][j2*2+jj][0], acc[i][j2*2+jj][1],
                                 acc[i][j2*2+jj][2], acc[i][j2*2+jj][3],
                                 Ah[i][0], Ah[i][1], Ah[i][2], Ah[i][3],
                                 B[jj*2], B[jj*2+1]);
                #pragma unroll
                for (int i = 0; i < 2; i++)
                    #pragma unroll
                    for (int jj = 0; jj < 2; jj++)
                        mma_bf16(acc[i][j2*2+jj][0], acc[i][j2*2+jj][1],
                                 acc[i][j2*2+jj][2], acc[i][j2*2+jj][3],
                                 Alr[i][0], Alr[i][1], Alr[i][2], Alr[i][3],
                                 B[jj*2], B[jj*2+1]);
                LDSM_X4(B[0], B[1], B[2], B[3], aWL + j2 * (16 * STR1B) + kb);
                #pragma unroll
                for (int i = 0; i < 2; i++)
                    #pragma unroll
                    for (int jj = 0; jj < 2; jj++)
                        mma_bf16(acc[i][j2*2+jj][0], acc[i][j2*2+jj][1],
                                 acc[i][j2*2+jj][2], acc[i][j2*2+jj][3],
                                 Ah[i][0], Ah[i][1], Ah[i][2], Ah[i][3],
                                 B[jj*2], B[jj*2+1]);
            }
        }

        // epilogue: BN + relu + split-bf16 store of z (overlaps inflight prefetch)
        uint32_t* zh = (uint32_t*)g_z_hi;
        uint32_t* zl = (uint32_t*)g_z_lo;
        #pragma unroll
        for (int i = 0; i < 2; i++) {
            #pragma unroll
            for (int hf = 0; hf < 2; hf++) {
                int r = row0 + m0 + i * 16 + (lane >> 2) + hf * 8;
                if (r < N_NODES) {
                    size_t rb = (size_t)r * 128 + (n0 >> 1) + q;
                    #pragma unroll
                    for (int j = 0; j < 4; j++) {
                        int c = n0 + j * 8 + 2 * q;
                        float z0 = fmaxf(fmaf(acc[i][j][hf * 2],     sAl[c],     sBe[c]),     0.f);
                        float z1 = fmaxf(fmaf(acc[i][j][hf * 2 + 1], sAl[c + 1], sBe[c + 1]), 0.f);
                        __nv_bfloat16 h0, h1, l0, l1;
                        split_bf(z0, h0, l0); split_bf(z1, h1, l1);
                        zh[rb + j * 4] = pack_bf(h0, h1);
                        zl[rb + j * 4] = pack_bf(l0, l1);
                    }
                }
            }
        }
        buf ^= 1;
    }
}

// ---------------- GEMM2: h = BN_o(z @ W2 + b2)(+relu),  [N,256]x[256,128] --------
// 512 thr, 16 warps: 2m x 8n, warp tile m32 x n16; M-tile 64; chunk double buffer
__global__ void __launch_bounds__(512, 1) k_gemm2(
    int layer, const float* __restrict__ bias,
    const float* __restrict__ bn_g, const float* __restrict__ bn_b,
    const float* __restrict__ bn_m, const float* __restrict__ bn_v,
    float* __restrict__ out, int relu)
{
    extern __shared__ char sm[];
    uint32_t sb = smem_u32(sm);
    int tid = threadIdx.x, lane = tid & 31, wid = tid >> 5;

    g2_issue(sb, tid, blockIdx.x << 6, 0, 0);   // chunk0 of first tile -> buf0

    {
        const uint4* s = (const uint4*)(g_w2t + (size_t)layer * 65536);
        #pragma unroll 2
        for (int i = tid; i < 4096; i += 512) {
            int r = i >> 5, c = i & 31;
            *(uint4*)(sm + G2_W + r * STR2B + c * 16) = s[i];
            *(uint4*)(sm + G2_WL + r * STR2B + c * 16) = s[i + 4096];
        }
    }
    float* sAl = (float*)(sm + G2_ALPHA);
    float* sBe = (float*)(sm + G2_BETA);
    if (tid < 128) {
        float s = bn_g[tid] * rsqrtf(bn_v[tid] + BN_EPS);
        sAl[tid] = s;
        sBe[tid] = (bias[tid] - bn_m[tid]) * s + bn_b[tid];
    }
    __syncthreads();

    int m0 = (wid >> 3) * 32, n0 = (wid & 7) * 16;
    uint32_t aoff = (uint32_t)((m0 + (lane & 15)) * STR1B + ((lane >> 4) << 4));
    uint32_t boff = (uint32_t)((n0 + ((lane >> 4) << 3) + (lane & 7)) * STR2B + (((lane >> 3) & 1) << 4));
    uint32_t aWH = sb + G2_W + boff;
    uint32_t aWL = sb + G2_WL + boff;
    int q = lane & 3;

    int buf = 0;
    for (int tile = blockIdx.x; tile < NT; tile += gridDim.x) {
        int row0 = tile << 6;

        float acc[2][2][4];
        #pragma unroll
        for (int i = 0; i < 2; i++)
            #pragma unroll
            for (int j = 0; j < 2; j++)
                #pragma unroll
                for (int f = 0; f < 4; f++) acc[i][j][f] = 0.f;

        #pragma unroll 1
        for (int ch = 0; ch < 2; ch++) {
            uint32_t chb = (uint32_t)ch * 256;
            CP_WAIT0();
            __syncthreads();
            // prefetch: next chunk of this tile, or chunk0 of next tile
            if (ch == 0) g2_issue(sb, tid, row0, 1, buf ^ 1);
            else         g2_issue(sb, tid, (tile + gridDim.x) << 6, 0, buf ^ 1);

            uint32_t aZH = sb + G2_Z + buf * G2_BUF + aoff;
            uint32_t aZL = aZH + G2_LO;

            #pragma unroll 2
            for (int ks = 0; ks < 8; ks++) {
                uint32_t kb = (uint32_t)ks << 5;
                uint32_t Ah[2][4], Alr[2][4], B[4];
                #pragma unroll
                for (int i = 0; i < 2; i++) {
                    LDSM_X4(Ah[i][0], Ah[i][1], Ah[i][2], Ah[i][3], aZH + i * (16 * STR1B) + kb);
                    LDSM_X4(Alr[i][0], Alr[i][1], Alr[i][2], Alr[i][3], aZL + i * (16 * STR1B) + kb);
                }
                LDSM_X4(B[0], B[1], B[2], B[3], aWH + chb + kb);
                #pragma unroll
                for (int i = 0; i < 2; i++)
                    #pragma unroll
                    for (int j = 0; j < 2; j++)
                        mma_bf16(acc[i][j][0], acc[i][j][1], acc[i][j][2], acc[i][j][3],
                                 Ah[i][0], Ah[i][1], Ah[i][2], Ah[i][3],
                                 B[j*2], B[j*2+1]);
                #pragma unroll
                for (int i = 0; i < 2; i++)
                    #pragma unroll
                    for (int j = 0; j < 2; j++)
                        mma_bf16(acc[i][j][0], acc[i][j][1], acc[i][j][2], acc[i][j][3],
                                 Alr[i][0], Alr[i][1], Alr[i][2], Alr[i][3],
                                 B[j*2], B[j*2+1]);
                LDSM_X4(B[0], B[1], B[2], B[3], aWL + chb + kb);
                #pragma unroll
                for (int i = 0; i < 2; i++)
                    #pragma unroll
                    for (int j = 0; j < 2; j++)
                        mma_bf16(acc[i][j][0], acc[i][j][1], acc[i][j][2], acc[i][j][3],
                                 Ah[i][0], Ah[i][1], Ah[i][2], Ah[i][3],
                                 B[j*2], B[j*2+1]);
            }
            buf ^= 1;
        }

        // epilogue: BN (+relu), fp32 store
        #pragma unroll
        for (int i = 0; i < 2; i++) {
            #pragma unroll
            for (int hf = 0; hf < 2; hf++) {
                int r = row0 + m0 + i * 16 + (lane >> 2) + hf * 8;
                if (r < N_NODES) {
                    float* dst = out + (size_t)r * 128;
                    #pragma unroll
                    for (int j = 0; j < 2; j++) {
                        int c = n0 + j * 8 + 2 * q;
                        float z0 = fmaf(acc[i][j][hf * 2],     sAl[c],     sBe[c]);
                        float z1 = fmaf(acc[i][j][hf * 2 + 1], sAl[c + 1], sBe[c + 1]);
                        if (relu) { z0 = fmaxf(z0, 0.f); z1 = fmaxf(z1, 0.f); }
                        *(float2*)(dst + c) = make_float2(z0, z1);
                    }
                }
            }
        }
    }
}

// ---------------- launch ----------------------------------------------------------
extern "C" void kernel_launch(void* const* d_in, const int* in_sizes, int n_in,
                              void* d_out, int out_size) {
    const float* x     = (const float*)d_in[0];
    const int*   ei    = (const int*)d_in[1];
    const float* W1    = (const float*)d_in[2];
    const float* b1    = (const float*)d_in[3];
    const float* bn1_g = (const float*)d_in[4];
    const float* bn1_b = (const float*)d_in[5];
    const float* bn1_m = (const float*)d_in[6];
    const float* bn1_v = (const float*)d_in[7];
    const float* W2    = (const float*)d_in[8];
    const float* b2    = (const float*)d_in[9];
    const float* bno_g = (const float*)d_in[10];
    const float* bno_b = (const float*)d_in[11];
    const float* bno_m = (const float*)d_in[12];
    const float* bno_v = (const float*)d_in[13];
    float* out = (float*)d_out;

    cudaFuncSetAttribute(k_gemm1, cudaFuncAttributeMaxDynamicSharedMemorySize, SMEM1);
    cudaFuncSetAttribute(k_gemm2, cudaFuncAttributeMaxDynamicSharedMemorySize, SMEM2);

    const int* src = ei;
    const int* dst = ei + EDGES;

    k_prep<<<1280, 256>>>(W1, W2);
    k_hist<<<(EDGES + 255) / 256, 256>>>(dst);
    k_scan_a<<<NSCAN, 1024>>>();
    k_scan_c<<<NSCAN, 1024>>>();
    k_fill<<<(EDGES + 255) / 256, 256>>>(src, dst);

    const float* h = x;
    for (int l = 0; l < LAYERS; l++) {
        k_aggregate<<<(N_NODES * 32 + 255) / 256, 256>>>(h);
        k_gemm1<<<GRID_G, 512, SMEM1>>>(l, b1 + (size_t)l * 256,
                bn1_g + (size_t)l * 256, bn1_b + (size_t)l * 256,
                bn1_m + (size_t)l * 256, bn1_v + (size_t)l * 256);
        k_gemm2<<<GRID_G, 512, SMEM2>>>(l, b2 + (size_t)l * 128,
                bno_g + (size_t)l * 128, bno_b + (size_t)l * 128,
                bno_m + (size_t)l * 128, bno_v + (size_t)l * 128,
                out, (l != LAYERS - 1) ? 1 : 0);
        h = out;
    }
}